// round 7
// baseline (speedup 1.0000x reference)
#include <cuda_runtime.h>
#include <cuda_fp16.h>
#include <cstdint>

// Problem constants
#define Bq   8
#define Sq   2048
#define Dq   1024
#define Hq   16
#define DHq  64
#define Mrows (Bq*Sq)        // 16384
#define BHn   (Bq*Hq)        // 128
#define OUT_MAIN (Mrows*Dq)  // 16777216 floats of `outputs`

__device__ float g_Tq[Mrows*32];
__device__ float g_Tk[Mrows*32];
__device__ float g_Q [Mrows*Dq];
__device__ float g_K [Mrows*Dq];
__device__ float g_V [Mrows*Dq];
__device__ float g_VV[BHn*DHq*DHq];
__device__ float g_VVV[Mrows*Dq];
__device__ float g_O1[Mrows*Dq];
__device__ float g_O2[Mrows*Dq];

// fp16 buffers for tensor-core GEMMs
__device__ __align__(128) __half g_Ah [Mrows*Dq];
__device__ __align__(128) __half g_Bh [Dq*Dq];   // transposed Wv  [n][k]
__device__ __align__(128) __half g_Bh2[Dq*Dq];   // transposed Wfc [n][k]

// ===========================================================================
// PTX helpers (sm_80/90 baseline — compile under compute_103)
// ===========================================================================
__device__ __forceinline__ uint32_t smem_u32(const void* p) {
    uint32_t a;
    asm("{ .reg .u64 t; cvta.to.shared.u64 t, %1; cvt.u32.u64 %0, t; }" : "=r"(a) : "l"(p));
    return a;
}
__device__ __forceinline__ void cpa16(uint32_t s, const void* g) {
    asm volatile("cp.async.cg.shared.global [%0], [%1], 16;" :: "r"(s), "l"(g));
}
__device__ __forceinline__ void cpa_commit() {
    asm volatile("cp.async.commit_group;" ::: "memory");
}
__device__ __forceinline__ void cpa_wait1() {
    asm volatile("cp.async.wait_group 1;" ::: "memory");
}
__device__ __forceinline__ void ldsm4(uint32_t* r, uint32_t addr) {
    asm volatile("ldmatrix.sync.aligned.m8n8.x4.shared.b16 {%0,%1,%2,%3}, [%4];"
                 : "=r"(r[0]), "=r"(r[1]), "=r"(r[2]), "=r"(r[3]) : "r"(addr));
}
__device__ __forceinline__ void mma16816(float* c, const uint32_t* a, const uint32_t* b) {
    asm volatile(
        "mma.sync.aligned.m16n8k16.row.col.f32.f16.f16.f32 "
        "{%0,%1,%2,%3}, {%4,%5,%6,%7}, {%8,%9}, {%0,%1,%2,%3};"
        : "+f"(c[0]), "+f"(c[1]), "+f"(c[2]), "+f"(c[3])
        : "r"(a[0]), "r"(a[1]), "r"(a[2]), "r"(a[3]), "r"(b[0]), "r"(b[1]));
}

// ===========================================================================
// HMMA GEMM: C[16384,1024] = A @ W  (fp16 x1), 512 threads, 16 warps of 32x32.
// K-chunk 64, 2-stage cp.async pipeline. selB picks g_Bh / g_Bh2.
// ===========================================================================
#define GP 72
#define ST_AH 0
#define ST_BH 18432                // 128*72*2
#define ST_BYTES 36864
#define HG_SMEM (2*ST_BYTES)

__device__ __forceinline__ void hg_load_stage(uint32_t sb, int st, const __half* gB,
                                              int m0, int n0, int kc, int tid) {
    uint32_t base = sb + st * ST_BYTES;
    #pragma unroll
    for (int i = 0; i < 2; i++) {
        int idx = tid + i * 512;
        int row = idx >> 3, c8 = idx & 7;
        uint32_t so = (uint32_t)(row * GP + c8 * 8) * 2;
        cpa16(base + ST_AH + so, g_Ah + (size_t)(m0 + row) * Dq + kc + c8 * 8);
        cpa16(base + ST_BH + so, gB   + (size_t)(n0 + row) * Dq + kc + c8 * 8);
    }
}

__global__ void __launch_bounds__(512) k_hgemm(float* __restrict__ C, int selB) {
    extern __shared__ char smem[];
    uint32_t sb = smem_u32(smem);
    const __half* gB = selB ? g_Bh2 : g_Bh;
    int tid = threadIdx.x;
    int lane = tid & 31, w = tid >> 5;
    int wm = w & 3, wn = w >> 2;
    int m0 = blockIdx.y * 128;
    int n0 = blockIdx.x * 128;

    float acc[2][4][4];
    #pragma unroll
    for (int i = 0; i < 2; i++)
        #pragma unroll
        for (int j = 0; j < 4; j++)
            #pragma unroll
            for (int k = 0; k < 4; k++) acc[i][j][k] = 0.f;

    hg_load_stage(sb, 0, gB, m0, n0, 0, tid);
    cpa_commit();
    hg_load_stage(sb, 1, gB, m0, n0, 64, tid);
    cpa_commit();
    cpa_wait1();
    __syncthreads();

    int aRow = lane & 15, aKo = (lane >> 4) << 3;
    int bRow = (lane & 7) + ((lane >> 4) << 3);
    int bKo = ((lane >> 3) & 1) << 3;

    for (int c = 0; c < 16; c++) {
        int st = c & 1;
        uint32_t s0 = sb + st * ST_BYTES;
        #pragma unroll
        for (int kh = 0; kh < 4; kh++) {
            uint32_t ah[2][4], bh[4][2];
            #pragma unroll
            for (int mt = 0; mt < 2; mt++) {
                uint32_t off = (uint32_t)((wm * 32 + mt * 16 + aRow) * GP + kh * 16 + aKo) * 2;
                ldsm4(ah[mt], s0 + ST_AH + off);
            }
            #pragma unroll
            for (int nt2 = 0; nt2 < 2; nt2++) {
                uint32_t off = (uint32_t)((wn * 32 + nt2 * 16 + bRow) * GP + kh * 16 + bKo) * 2;
                uint32_t r[4];
                ldsm4(r, s0 + ST_BH + off);
                bh[nt2*2][0] = r[0]; bh[nt2*2][1] = r[1];
                bh[nt2*2+1][0] = r[2]; bh[nt2*2+1][1] = r[3];
            }
            #pragma unroll
            for (int mt = 0; mt < 2; mt++)
                #pragma unroll
                for (int nt = 0; nt < 4; nt++) mma16816(acc[mt][nt], ah[mt], bh[nt]);
        }
        __syncthreads();
        if (c + 2 < 16)
            hg_load_stage(sb, st, gB, m0, n0, (c + 2) * 64, tid);
        cpa_commit();
        cpa_wait1();
        __syncthreads();
    }

    #pragma unroll
    for (int mt = 0; mt < 2; mt++) {
        int r0 = m0 + wm * 32 + mt * 16 + (lane >> 2);
        #pragma unroll
        for (int nt = 0; nt < 4; nt++) {
            int col = n0 + wn * 32 + nt * 8 + (lane & 3) * 2;
            *(float2*)(C + (size_t)r0 * Dq + col)       = make_float2(acc[mt][nt][0], acc[mt][nt][1]);
            *(float2*)(C + (size_t)(r0 + 8) * Dq + col) = make_float2(acc[mt][nt][2], acc[mt][nt][3]);
        }
    }
}

// ===========================================================================
// fp32 -> fp16 convert into g_Ah
// ===========================================================================
__global__ void k_half(const float* __restrict__ x) {
    size_t i = ((size_t)blockIdx.x * 256 + threadIdx.x) * 4;
    float4 v = *(const float4*)(x + i);
    *(__half2*)(g_Ah + i)     = __floats2half2_rn(v.x, v.y);
    *(__half2*)(g_Ah + i + 2) = __floats2half2_rn(v.z, v.w);
}

// ===========================================================================
// fp32 W[k][n] -> transposed fp16 Wt[n][k], sel picks g_Bh / g_Bh2
// ===========================================================================
__global__ void k_halfT(const float* __restrict__ W, int sel) {
    __shared__ float t[32][33];
    __half* dst = sel ? g_Bh2 : g_Bh;
    int tx = threadIdx.x, ty = threadIdx.y;
    int bx = blockIdx.x, by = blockIdx.y;
    #pragma unroll
    for (int i = 0; i < 4; i++)
        t[ty + i*8][tx] = W[(size_t)(by*32 + ty + i*8) * Dq + bx*32 + tx];
    __syncthreads();
    #pragma unroll
    for (int i = 0; i < 4; i++) {
        size_t o = (size_t)(bx*32 + ty + i*8) * Dq + by*32 + tx;
        dst[o] = __float2half(t[tx][ty + i*8]);
    }
}

// ---------------------------------------------------------------------------
// proj1: T = X @ W1   (X: [16384,1024], W1: [1024,32])
// ---------------------------------------------------------------------------
__global__ void k_proj1(const float* __restrict__ X, const float* __restrict__ W, int sel) {
    __shared__ float Xs[64][64];
    __shared__ float Ws[64][32];
    float* T = sel ? g_Tk : g_Tq;
    int t = threadIdx.x;
    int row0 = blockIdx.x * 64;
    int tr = t >> 5, tc = t & 31;
    float acc[8];
    #pragma unroll
    for (int i = 0; i < 8; i++) acc[i] = 0.f;
    for (int kc = 0; kc < 1024; kc += 64) {
        #pragma unroll
        for (int i = 0; i < 4; i++) {
            int idx = t + i * 256;
            int r = idx >> 4, c = idx & 15;
            *(float4*)&Xs[r][c*4] = *(const float4*)(X + (size_t)(row0 + r) * 1024 + kc + c*4);
        }
        #pragma unroll
        for (int i = 0; i < 2; i++) {
            int idx = t + i * 256;
            int k = idx >> 3, c = idx & 7;
            *(float4*)&Ws[k][c*4] = *(const float4*)(W + (size_t)(kc + k) * 32 + c*4);
        }
        __syncthreads();
        #pragma unroll
        for (int k = 0; k < 64; k += 4) {
            float w0 = Ws[k][tc], w1 = Ws[k+1][tc], w2 = Ws[k+2][tc], w3 = Ws[k+3][tc];
            #pragma unroll
            for (int i = 0; i < 8; i++) {
                float4 x = *(const float4*)&Xs[tr*8 + i][k];
                acc[i] += x.x*w0 + x.y*w1 + x.z*w2 + x.w*w3;
            }
        }
        __syncthreads();
    }
    #pragma unroll
    for (int i = 0; i < 8; i++)
        T[(size_t)(row0 + tr*8 + i) * 32 + tc] = acc[i];
}

// ---------------------------------------------------------------------------
// proj2: O = T @ W2   (T: [16384,32], W2: [32,1024])
// ---------------------------------------------------------------------------
__global__ void k_proj2(const float* __restrict__ W2, int sel) {
    __shared__ float Ts[64][33];
    __shared__ float Ws[32][132];
    const float* T = sel ? g_Tk : g_Tq;
    float* O = sel ? g_K : g_Q;
    int t = threadIdx.x;
    int row0 = blockIdx.y * 64;
    int n0 = blockIdx.x * 128;
    #pragma unroll
    for (int i = 0; i < 2; i++) {
        int idx = (t + i * 256) * 4;
        int r = idx >> 5, k = idx & 31;
        float4 v = *(const float4*)(T + (size_t)(row0 + r) * 32 + k);
        Ts[r][k] = v.x; Ts[r][k+1] = v.y; Ts[r][k+2] = v.z; Ts[r][k+3] = v.w;
    }
    #pragma unroll
    for (int i = 0; i < 4; i++) {
        int idx = (t + i * 256) * 4;
        int k = idx >> 7, c = idx & 127;
        *(float4*)&Ws[k][c] = *(const float4*)(W2 + (size_t)k * 1024 + n0 + c);
    }
    __syncthreads();
    int tr = t >> 5, tc = t & 31;
    float acc[8][4];
    #pragma unroll
    for (int i = 0; i < 8; i++)
        #pragma unroll
        for (int j = 0; j < 4; j++) acc[i][j] = 0.f;
    #pragma unroll
    for (int k = 0; k < 32; k++) {
        float4 wv = *(const float4*)&Ws[k][tc*4];
        #pragma unroll
        for (int i = 0; i < 8; i++) {
            float tv = Ts[tr*8 + i][k];
            acc[i][0] += tv * wv.x;
            acc[i][1] += tv * wv.y;
            acc[i][2] += tv * wv.z;
            acc[i][3] += tv * wv.w;
        }
    }
    #pragma unroll
    for (int i = 0; i < 8; i++)
        *(float4*)(O + (size_t)(row0 + tr*8 + i) * 1024 + n0 + tc*4) =
            make_float4(acc[i][0], acc[i][1], acc[i][2], acc[i][3]);
}

// ---------------------------------------------------------------------------
// scores: attn[b,h,d,s] = scale * sum_f A[f,d] * K[b,h,s,f]
// ---------------------------------------------------------------------------
__global__ void k_scores(const float* __restrict__ Amat, float* __restrict__ attn) {
    __shared__ float Asm[64][68];
    __shared__ float Ksm[64][68];
    int bh = blockIdx.y;
    int b = bh >> 4, h = bh & 15;
    int s0 = blockIdx.x * 64;
    int t = threadIdx.x;
    for (int i = t; i < 4096; i += 256) {
        int f = i >> 6, d = i & 63;
        Asm[d][f] = Amat[i];
    }
    for (int i = t; i < 4096; i += 256) {
        int sl = i >> 6, f = i & 63;
        Ksm[sl][f] = g_K[(size_t)(b * Sq + s0 + sl) * 1024 + h * 64 + f];
    }
    __syncthreads();
    int sl = t & 63, dg = t >> 6;
    float acc[16];
    #pragma unroll
    for (int i = 0; i < 16; i++) acc[i] = 0.f;
    #pragma unroll
    for (int f4 = 0; f4 < 16; f4++) {
        float4 kv = *(const float4*)&Ksm[sl][f4*4];
        #pragma unroll
        for (int dd = 0; dd < 16; dd++) {
            float4 av = *(const float4*)&Asm[dg*16 + dd][f4*4];
            acc[dd] += kv.x*av.x + kv.y*av.y + kv.z*av.z + kv.w*av.w;
        }
    }
    #pragma unroll
    for (int dd = 0; dd < 16; dd++) {
        int d = dg * 16 + dd;
        attn[((size_t)(bh * 64 + d)) * Sq + s0 + sl] = acc[dd] * 0.125f;
    }
}

// ---------------------------------------------------------------------------
// softmax over s (row length 2048), in place.
// ---------------------------------------------------------------------------
__global__ void k_softmax(float* __restrict__ attn) {
    __shared__ float smx[8];
    __shared__ float sms[8];
    float* p = attn + (size_t)blockIdx.x * Sq;
    int t = threadIdx.x;
    float v[8];
    float m = -1e30f;
    #pragma unroll
    for (int i = 0; i < 8; i++) { v[i] = p[t + i * 256]; m = fmaxf(m, v[i]); }
    #pragma unroll
    for (int o = 16; o > 0; o >>= 1) m = fmaxf(m, __shfl_xor_sync(0xffffffffu, m, o));
    if ((t & 31) == 0) smx[t >> 5] = m;
    __syncthreads();
    m = smx[0];
    #pragma unroll
    for (int i = 1; i < 8; i++) m = fmaxf(m, smx[i]);
    float l = 0.f;
    #pragma unroll
    for (int i = 0; i < 8; i++) { v[i] = __expf(v[i] - m); l += v[i]; }
    #pragma unroll
    for (int o = 16; o > 0; o >>= 1) l += __shfl_xor_sync(0xffffffffu, l, o);
    if ((t & 31) == 0) sms[t >> 5] = l;
    __syncthreads();
    l = 0.f;
    #pragma unroll
    for (int i = 0; i < 8; i++) l += sms[i];
    float inv = 1.f / l;
    #pragma unroll
    for (int i = 0; i < 8; i++) p[t + i * 256] = v[i] * inv;
}

// ---------------------------------------------------------------------------
// VV[bh][d][f] += sum_{s in split} attn[bh,d,s] * V[b,s,h*64+f]
// ---------------------------------------------------------------------------
__global__ void k_vv(const float* __restrict__ attn) {
    __shared__ float At[64][65];
    __shared__ float Vs[64][65];
    int split = blockIdx.x;
    int bh = blockIdx.y;
    int b = bh >> 4, h = bh & 15;
    int t = threadIdx.x;
    int tr = t >> 4, tc = t & 15;
    float acc[4][4];
    #pragma unroll
    for (int i = 0; i < 4; i++)
        #pragma unroll
        for (int j = 0; j < 4; j++) acc[i][j] = 0.f;
    int sbeg = split * 512;
    for (int sc0 = sbeg; sc0 < sbeg + 512; sc0 += 64) {
        for (int i = t; i < 4096; i += 256) {
            int d = i >> 6, ss = i & 63;
            At[d][ss] = attn[((size_t)(bh * 64 + d)) * Sq + sc0 + ss];
        }
        for (int i = t; i < 4096; i += 256) {
            int ss = i >> 6, f = i & 63;
            Vs[ss][f] = g_V[(size_t)(b * Sq + sc0 + ss) * 1024 + h * 64 + f];
        }
        __syncthreads();
        #pragma unroll 8
        for (int ss = 0; ss < 64; ss++) {
            float av[4], bv[4];
            #pragma unroll
            for (int i = 0; i < 4; i++) av[i] = At[tr * 4 + i][ss];
            #pragma unroll
            for (int j = 0; j < 4; j++) bv[j] = Vs[ss][tc * 4 + j];
            #pragma unroll
            for (int i = 0; i < 4; i++)
                #pragma unroll
                for (int j = 0; j < 4; j++) acc[i][j] += av[i] * bv[j];
        }
        __syncthreads();
    }
    #pragma unroll
    for (int i = 0; i < 4; i++)
        #pragma unroll
        for (int j = 0; j < 4; j++)
            atomicAdd(&g_VV[(size_t)bh * 4096 + (tr * 4 + i) * 64 + tc * 4 + j], acc[i][j]);
}

// ---------------------------------------------------------------------------
// stage 2: two-pass softmax, float4 LDS, halves for output.
// ---------------------------------------------------------------------------
__global__ void k_stage2(const float* __restrict__ Amat) {
    __shared__ float Asm[64][68];
    __shared__ float VVs[64][68];
    int bh = blockIdx.y;
    int b = bh >> 4, h = bh & 15;
    int s0 = blockIdx.x * 128;
    int t = threadIdx.x;
    for (int i = t; i < 4096; i += 128) {
        int d = i >> 6, f = i & 63;
        Asm[d][f] = Amat[i];
        VVs[d][f] = g_VV[(size_t)bh * 4096 + i];
    }
    __syncthreads();
    int s = s0 + t;
    const float* Qrow = g_Q + (size_t)(b * Sq + s) * 1024 + h * 64;
    float qr[64];
    #pragma unroll
    for (int f4 = 0; f4 < 64; f4 += 4) {
        float4 q = *(const float4*)(Qrow + f4);
        qr[f4] = q.x; qr[f4+1] = q.y; qr[f4+2] = q.z; qr[f4+3] = q.w;
    }
    float sc[64];
    #pragma unroll
    for (int d = 0; d < 64; d++) {
        float sum = 0.f;
        #pragma unroll
        for (int f4 = 0; f4 < 16; f4++) {
            float4 av = *(const float4*)&Asm[d][f4*4];
            sum += qr[f4*4]*av.x + qr[f4*4+1]*av.y + qr[f4*4+2]*av.z + qr[f4*4+3]*av.w;
        }
        sc[d] = sum * 0.125f;
    }
    float m = sc[0];
    #pragma unroll
    for (int d = 1; d < 64; d++) m = fmaxf(m, sc[d]);
    float l = 0.f;
    #pragma unroll
    for (int d = 0; d < 64; d++) { float e = __expf(sc[d] - m); sc[d] = e; l += e; }
    float inv = 1.f / l;
    float* Orow = g_VVV + ((size_t)bh * Sq + s) * 64;
    #pragma unroll
    for (int half = 0; half < 2; half++) {
        float out[32];
        #pragma unroll
        for (int j = 0; j < 32; j++) out[j] = 0.f;
        #pragma unroll 8
        for (int d = 0; d < 64; d++) {
            float p = sc[d];
            #pragma unroll
            for (int f4 = 0; f4 < 8; f4++) {
                float4 vv = *(const float4*)&VVs[d][half*32 + f4*4];
                out[f4*4]   += p * vv.x;
                out[f4*4+1] += p * vv.y;
                out[f4*4+2] += p * vv.z;
                out[f4*4+3] += p * vv.w;
            }
        }
        #pragma unroll
        for (int j = 0; j < 32; j += 4)
            *(float4*)(Orow + half*32 + j) = make_float4(out[j]*inv, out[j+1]*inv,
                                                         out[j+2]*inv, out[j+3]*inv);
    }
}

// ---------------------------------------------------------------------------
// LayerNorm over last dim (1024), x = in1 + res.
// sel=0: in1=g_VVV, res=Xq, out=g_O1, ALSO emits fp16 to g_Ah.
// sel=1: in1=g_O2,  res=g_O1, out=d_out.
// ---------------------------------------------------------------------------
__global__ void k_ln(const float* __restrict__ rese, const float* __restrict__ g,
                     const float* __restrict__ bb, float* __restrict__ oute, int sel) {
    const float* in1 = sel ? g_O2 : g_VVV;
    const float* res = sel ? g_O1 : rese;
    float* out = sel ? oute : g_O1;
    __shared__ float sm1[8];
    __shared__ float sm2[8];
    size_t base = (size_t)blockIdx.x * 1024;
    int t = threadIdx.x;
    float v[4];
    float sum = 0.f;
    #pragma unroll
    for (int i = 0; i < 4; i++) {
        int c = t + i * 256;
        v[i] = in1[base + c] + res[base + c];
        sum += v[i];
    }
    #pragma unroll
    for (int o = 16; o > 0; o >>= 1) sum += __shfl_xor_sync(0xffffffffu, sum, o);
    if ((t & 31) == 0) sm1[t >> 5] = sum;
    __syncthreads();
    sum = 0.f;
    #pragma unroll
    for (int i = 0; i < 8; i++) sum += sm1[i];
    float mean = sum * (1.f / 1024.f);
    float sq = 0.f;
    #pragma unroll
    for (int i = 0; i < 4; i++) { float d = v[i] - mean; sq += d * d; }
    #pragma unroll
    for (int o = 16; o > 0; o >>= 1) sq += __shfl_xor_sync(0xffffffffu, sq, o);
    if ((t & 31) == 0) sm2[t >> 5] = sq;
    __syncthreads();
    sq = 0.f;
    #pragma unroll
    for (int i = 0; i < 8; i++) sq += sm2[i];
    float rstd = rsqrtf(sq * (1.f / 1024.f) + 1e-5f);
    #pragma unroll
    for (int i = 0; i < 4; i++) {
        int c = t + i * 256;
        float o = (v[i] - mean) * rstd * g[c] + bb[c];
        out[base + c] = o;
        if (sel == 0) g_Ah[base + c] = __float2half(o);
    }
}

// ===========================================================================
// Host side — fork/join two streams inside graph capture.
// ===========================================================================
extern "C" void kernel_launch(void* const* d_in, const int* in_sizes, int n_in,
                              void* d_out, int out_size) {
    const float* Xq  = (const float*)d_in[0];
    const float* Xk  = (const float*)d_in[1];
    const float* Xv  = (const float*)d_in[2];
    const float* Wq1 = (const float*)d_in[3];
    const float* Wq2 = (const float*)d_in[4];
    const float* Wk1 = (const float*)d_in[5];
    const float* Wk2 = (const float*)d_in[6];
    const float* Wv  = (const float*)d_in[7];
    const float* Wfc = (const float*)d_in[8];
    const float* Am  = (const float*)d_in[9];
    const float* lng = (const float*)d_in[10];
    const float* lnb = (const float*)d_in[11];
    float* out = (float*)d_out;
    size_t attn_off = (out_size > OUT_MAIN) ? (size_t)(out_size - OUT_MAIN) : 0;
    float* attn = out + attn_off;

    void *pV, *pO2, *pVV;
    cudaGetSymbolAddress(&pV,  g_V);
    cudaGetSymbolAddress(&pO2, g_O2);
    cudaGetSymbolAddress(&pVV, g_VV);

    static cudaStream_t sA = nullptr, sB = nullptr;
    static cudaEvent_t eFork = nullptr, eA = nullptr, eB = nullptr;
    if (sA == nullptr) {
        cudaStreamCreateWithFlags(&sA, cudaStreamNonBlocking);
        cudaStreamCreateWithFlags(&sB, cudaStreamNonBlocking);
        cudaEventCreateWithFlags(&eFork, cudaEventDisableTiming);
        cudaEventCreateWithFlags(&eA, cudaEventDisableTiming);
        cudaEventCreateWithFlags(&eB, cudaEventDisableTiming);
    }

    cudaFuncSetAttribute(k_hgemm, cudaFuncAttributeMaxDynamicSharedMemorySize, HG_SMEM);

    // fork from the capture-origin (default) stream
    cudaEventRecord(eFork, 0);
    cudaStreamWaitEvent(sA, eFork, 0);
    cudaStreamWaitEvent(sB, eFork, 0);

    // ---- stream A: V GEMM chain + Wfc conversion ----
    k_half<<<16384, 256, 0, sA>>>(Xv);
    k_halfT<<<dim3(32, 32), dim3(32, 8), 0, sA>>>(Wv, 0);
    k_hgemm<<<dim3(8, 128), 512, HG_SMEM, sA>>>((float*)pV, 0);
    k_halfT<<<dim3(32, 32), dim3(32, 8), 0, sA>>>(Wfc, 1);
    cudaEventRecord(eA, sA);

    // ---- stream B: Q/K projections -> scores -> softmax ----
    k_proj1<<<256, 256, 0, sB>>>(Xq, Wq1, 0);
    k_proj1<<<256, 256, 0, sB>>>(Xk, Wk1, 1);
    k_proj2<<<dim3(8, 256), 256, 0, sB>>>(Wq2, 0);
    k_proj2<<<dim3(8, 256), 256, 0, sB>>>(Wk2, 1);
    k_scores<<<dim3(32, 128), 256, 0, sB>>>(Am, attn);
    k_softmax<<<8192, 256, 0, sB>>>(attn);
    cudaMemsetAsync(pVV, 0, (size_t)BHn * DHq * DHq * sizeof(float), sB);

    // ---- join: tail needs both V (sA) and softmaxed attn (sB) ----
    cudaStreamWaitEvent(sB, eA, 0);
    k_vv<<<dim3(4, 128), 256, 0, sB>>>(attn);
    k_stage2<<<dim3(16, 128), 128, 0, sB>>>(Am);
    k_ln<<<16384, 256, 0, sB>>>(Xq, lng, lnb, nullptr, 0);   // out1 = LN(VVV+Xq) + fp16
    k_hgemm<<<dim3(8, 128), 512, HG_SMEM, sB>>>((float*)pO2, 1);
    k_ln<<<16384, 256, 0, sB>>>(nullptr, lng, lnb, out, 1);  // out = LN(out2 + out1)
    cudaEventRecord(eB, sB);

    // join back to capture-origin stream
    cudaStreamWaitEvent(0, eB, 0);
}

// round 8
// speedup vs baseline: 1.1372x; 1.1372x over previous
#include <cuda_runtime.h>
#include <cuda_fp16.h>
#include <cstdint>

// Problem constants
#define Bq   8
#define Sq   2048
#define Dq   1024
#define Hq   16
#define DHq  64
#define Mrows (Bq*Sq)        // 16384
#define BHn   (Bq*Hq)        // 128
#define OUT_MAIN (Mrows*Dq)  // 16777216 floats of `outputs`

__device__ float g_Tq[Mrows*32];
__device__ float g_Tk[Mrows*32];
__device__ float g_Q [Mrows*Dq];
__device__ float g_K [Mrows*Dq];
__device__ float g_VV[BHn*DHq*DHq];
__device__ float g_VVV[Mrows*Dq];
__device__ float g_O1[Mrows*Dq];
__device__ float g_O2[Mrows*Dq];

// fp16 buffers
__device__ __align__(128) __half g_Ah [Mrows*Dq];   // A operand of hgemm
__device__ __align__(128) __half g_Vh [Mrows*Dq];   // V in fp16 (hgemm1 output)
__device__ __align__(128) __half g_Bh [Dq*Dq];      // transposed Wv  [n][k]
__device__ __align__(128) __half g_Bh2[Dq*Dq];      // transposed Wfc [n][k]

// ===========================================================================
// PTX helpers (sm_80/90 baseline — compile under compute_103)
// ===========================================================================
__device__ __forceinline__ uint32_t smem_u32(const void* p) {
    uint32_t a;
    asm("{ .reg .u64 t; cvta.to.shared.u64 t, %1; cvt.u32.u64 %0, t; }" : "=r"(a) : "l"(p));
    return a;
}
__device__ __forceinline__ void cpa16(uint32_t s, const void* g) {
    asm volatile("cp.async.cg.shared.global [%0], [%1], 16;" :: "r"(s), "l"(g));
}
__device__ __forceinline__ void cpa_commit() {
    asm volatile("cp.async.commit_group;" ::: "memory");
}
__device__ __forceinline__ void cpa_wait1() {
    asm volatile("cp.async.wait_group 1;" ::: "memory");
}
__device__ __forceinline__ void ldsm4(uint32_t* r, uint32_t addr) {
    asm volatile("ldmatrix.sync.aligned.m8n8.x4.shared.b16 {%0,%1,%2,%3}, [%4];"
                 : "=r"(r[0]), "=r"(r[1]), "=r"(r[2]), "=r"(r[3]) : "r"(addr));
}
__device__ __forceinline__ void mma16816(float* c, const uint32_t* a, const uint32_t* b) {
    asm volatile(
        "mma.sync.aligned.m16n8k16.row.col.f32.f16.f16.f32 "
        "{%0,%1,%2,%3}, {%4,%5,%6,%7}, {%8,%9}, {%0,%1,%2,%3};"
        : "+f"(c[0]), "+f"(c[1]), "+f"(c[2]), "+f"(c[3])
        : "r"(a[0]), "r"(a[1]), "r"(a[2]), "r"(a[3]), "r"(b[0]), "r"(b[1]));
}

// ===========================================================================
// HMMA GEMM: C = A @ W (fp16 x1), 512 threads, 16 warps of 32x32, K-chunk 64.
// sel=0: B=g_Bh, output fp16 -> g_Vh.  sel=1: B=g_Bh2, output fp32 -> C.
// ===========================================================================
#define GP 72
#define ST_AH 0
#define ST_BH 18432
#define ST_BYTES 36864
#define HG_SMEM (2*ST_BYTES)

__device__ __forceinline__ void hg_load_stage(uint32_t sb, int st, const __half* gB,
                                              int m0, int n0, int kc, int tid) {
    uint32_t base = sb + st * ST_BYTES;
    #pragma unroll
    for (int i = 0; i < 2; i++) {
        int idx = tid + i * 512;
        int row = idx >> 3, c8 = idx & 7;
        uint32_t so = (uint32_t)(row * GP + c8 * 8) * 2;
        cpa16(base + ST_AH + so, g_Ah + (size_t)(m0 + row) * Dq + kc + c8 * 8);
        cpa16(base + ST_BH + so, gB   + (size_t)(n0 + row) * Dq + kc + c8 * 8);
    }
}

__global__ void __launch_bounds__(512) k_hgemm(float* __restrict__ C, int sel) {
    extern __shared__ char smem[];
    uint32_t sb = smem_u32(smem);
    const __half* gB = sel ? g_Bh2 : g_Bh;
    int tid = threadIdx.x;
    int lane = tid & 31, w = tid >> 5;
    int wm = w & 3, wn = w >> 2;
    int m0 = blockIdx.y * 128;
    int n0 = blockIdx.x * 128;

    float acc[2][4][4];
    #pragma unroll
    for (int i = 0; i < 2; i++)
        #pragma unroll
        for (int j = 0; j < 4; j++)
            #pragma unroll
            for (int k = 0; k < 4; k++) acc[i][j][k] = 0.f;

    hg_load_stage(sb, 0, gB, m0, n0, 0, tid);
    cpa_commit();
    hg_load_stage(sb, 1, gB, m0, n0, 64, tid);
    cpa_commit();
    cpa_wait1();
    __syncthreads();

    int aRow = lane & 15, aKo = (lane >> 4) << 3;
    int bRow = (lane & 7) + ((lane >> 4) << 3);
    int bKo = ((lane >> 3) & 1) << 3;

    for (int c = 0; c < 16; c++) {
        int st = c & 1;
        uint32_t s0 = sb + st * ST_BYTES;
        #pragma unroll
        for (int kh = 0; kh < 4; kh++) {
            uint32_t ah[2][4], bh[4][2];
            #pragma unroll
            for (int mt = 0; mt < 2; mt++) {
                uint32_t off = (uint32_t)((wm * 32 + mt * 16 + aRow) * GP + kh * 16 + aKo) * 2;
                ldsm4(ah[mt], s0 + ST_AH + off);
            }
            #pragma unroll
            for (int nt2 = 0; nt2 < 2; nt2++) {
                uint32_t off = (uint32_t)((wn * 32 + nt2 * 16 + bRow) * GP + kh * 16 + bKo) * 2;
                uint32_t r[4];
                ldsm4(r, s0 + ST_BH + off);
                bh[nt2*2][0] = r[0]; bh[nt2*2][1] = r[1];
                bh[nt2*2+1][0] = r[2]; bh[nt2*2+1][1] = r[3];
            }
            #pragma unroll
            for (int mt = 0; mt < 2; mt++)
                #pragma unroll
                for (int nt = 0; nt < 4; nt++) mma16816(acc[mt][nt], ah[mt], bh[nt]);
        }
        __syncthreads();
        if (c + 2 < 16)
            hg_load_stage(sb, st, gB, m0, n0, (c + 2) * 64, tid);
        cpa_commit();
        cpa_wait1();
        __syncthreads();
    }

    if (sel == 0) {
        #pragma unroll
        for (int mt = 0; mt < 2; mt++) {
            int r0 = m0 + wm * 32 + mt * 16 + (lane >> 2);
            #pragma unroll
            for (int nt = 0; nt < 4; nt++) {
                int col = n0 + wn * 32 + nt * 8 + (lane & 3) * 2;
                *(__half2*)(g_Vh + (size_t)r0 * Dq + col) =
                    __floats2half2_rn(acc[mt][nt][0], acc[mt][nt][1]);
                *(__half2*)(g_Vh + (size_t)(r0 + 8) * Dq + col) =
                    __floats2half2_rn(acc[mt][nt][2], acc[mt][nt][3]);
            }
        }
    } else {
        #pragma unroll
        for (int mt = 0; mt < 2; mt++) {
            int r0 = m0 + wm * 32 + mt * 16 + (lane >> 2);
            #pragma unroll
            for (int nt = 0; nt < 4; nt++) {
                int col = n0 + wn * 32 + nt * 8 + (lane & 3) * 2;
                *(float2*)(C + (size_t)r0 * Dq + col)       = make_float2(acc[mt][nt][0], acc[mt][nt][1]);
                *(float2*)(C + (size_t)(r0 + 8) * Dq + col) = make_float2(acc[mt][nt][2], acc[mt][nt][3]);
            }
        }
    }
}

// ===========================================================================
// fp32 -> fp16 convert into g_Ah
// ===========================================================================
__global__ void k_half(const float* __restrict__ x) {
    size_t i = ((size_t)blockIdx.x * 256 + threadIdx.x) * 4;
    float4 v = *(const float4*)(x + i);
    *(__half2*)(g_Ah + i)     = __floats2half2_rn(v.x, v.y);
    *(__half2*)(g_Ah + i + 2) = __floats2half2_rn(v.z, v.w);
}

// ===========================================================================
// fp32 W[k][n] -> transposed fp16 Wt[n][k], sel picks g_Bh / g_Bh2
// ===========================================================================
__global__ void k_halfT(const float* __restrict__ W, int sel) {
    __shared__ float t[32][33];
    __half* dst = sel ? g_Bh2 : g_Bh;
    int tx = threadIdx.x, ty = threadIdx.y;
    int bx = blockIdx.x, by = blockIdx.y;
    #pragma unroll
    for (int i = 0; i < 4; i++)
        t[ty + i*8][tx] = W[(size_t)(by*32 + ty + i*8) * Dq + bx*32 + tx];
    __syncthreads();
    #pragma unroll
    for (int i = 0; i < 4; i++) {
        size_t o = (size_t)(bx*32 + ty + i*8) * Dq + by*32 + tx;
        dst[o] = __float2half(t[tx][ty + i*8]);
    }
}

// ---------------------------------------------------------------------------
// proj1: T = X @ W1.  32 rows/block (512 blocks), k-chunk 64, 4 acc/thread.
// ---------------------------------------------------------------------------
__global__ void k_proj1(const float* __restrict__ X, const float* __restrict__ W, int sel) {
    __shared__ float Xs[32][64];
    __shared__ float Ws[64][32];
    float* T = sel ? g_Tk : g_Tq;
    int t = threadIdx.x;
    int row0 = blockIdx.x * 32;
    int tr = t >> 5, tc = t & 31;
    float acc[4] = {0.f, 0.f, 0.f, 0.f};
    for (int kc = 0; kc < 1024; kc += 64) {
        #pragma unroll
        for (int i = 0; i < 2; i++) {
            int idx = t + i * 256;                 // 0..511 float4 of X tile
            int r = idx >> 4, c4 = idx & 15;
            *(float4*)&Xs[r][c4*4] = *(const float4*)(X + (size_t)(row0 + r) * 1024 + kc + c4*4);
        }
        #pragma unroll
        for (int i = 0; i < 2; i++) {
            int idx = t + i * 256;                 // 0..511 float4 of W chunk
            int k = idx >> 3, c = (idx & 7) * 4;
            *(float4*)&Ws[k][c] = *(const float4*)(W + (size_t)(kc + k) * 32 + c);
        }
        __syncthreads();
        #pragma unroll
        for (int k = 0; k < 64; k += 4) {
            float w0 = Ws[k][tc], w1 = Ws[k+1][tc], w2 = Ws[k+2][tc], w3 = Ws[k+3][tc];
            #pragma unroll
            for (int i = 0; i < 4; i++) {
                float4 x = *(const float4*)&Xs[tr*4 + i][k];
                acc[i] += x.x*w0 + x.y*w1 + x.z*w2 + x.w*w3;
            }
        }
        __syncthreads();
    }
    #pragma unroll
    for (int i = 0; i < 4; i++)
        T[(size_t)(row0 + tr*4 + i) * 32 + tc] = acc[i];
}

// ---------------------------------------------------------------------------
// proj2: O = T @ W2   (T: [16384,32], W2: [32,1024])
// ---------------------------------------------------------------------------
__global__ void k_proj2(const float* __restrict__ W2, int sel) {
    __shared__ float Ts[64][33];
    __shared__ float Ws[32][132];
    const float* T = sel ? g_Tk : g_Tq;
    float* O = sel ? g_K : g_Q;
    int t = threadIdx.x;
    int row0 = blockIdx.y * 64;
    int n0 = blockIdx.x * 128;
    #pragma unroll
    for (int i = 0; i < 2; i++) {
        int idx = (t + i * 256) * 4;
        int r = idx >> 5, k = idx & 31;
        float4 v = *(const float4*)(T + (size_t)(row0 + r) * 32 + k);
        Ts[r][k] = v.x; Ts[r][k+1] = v.y; Ts[r][k+2] = v.z; Ts[r][k+3] = v.w;
    }
    #pragma unroll
    for (int i = 0; i < 4; i++) {
        int idx = (t + i * 256) * 4;
        int k = idx >> 7, c = idx & 127;
        *(float4*)&Ws[k][c] = *(const float4*)(W2 + (size_t)k * 1024 + n0 + c);
    }
    __syncthreads();
    int tr = t >> 5, tc = t & 31;
    float acc[8][4];
    #pragma unroll
    for (int i = 0; i < 8; i++)
        #pragma unroll
        for (int j = 0; j < 4; j++) acc[i][j] = 0.f;
    #pragma unroll
    for (int k = 0; k < 32; k++) {
        float4 wv = *(const float4*)&Ws[k][tc*4];
        #pragma unroll
        for (int i = 0; i < 8; i++) {
            float tv = Ts[tr*8 + i][k];
            acc[i][0] += tv * wv.x;
            acc[i][1] += tv * wv.y;
            acc[i][2] += tv * wv.z;
            acc[i][3] += tv * wv.w;
        }
    }
    #pragma unroll
    for (int i = 0; i < 8; i++)
        *(float4*)(O + (size_t)(row0 + tr*8 + i) * 1024 + n0 + tc*4) =
            make_float4(acc[i][0], acc[i][1], acc[i][2], acc[i][3]);
}

// ---------------------------------------------------------------------------
// scores: attn[b,h,d,s] = scale * sum_f A[f,d] * K[b,h,s,f]  (fp32, attn is output)
// ---------------------------------------------------------------------------
__global__ void k_scores(const float* __restrict__ Amat, float* __restrict__ attn) {
    __shared__ float Asm[64][68];
    __shared__ float Ksm[64][68];
    int bh = blockIdx.y;
    int b = bh >> 4, h = bh & 15;
    int s0 = blockIdx.x * 64;
    int t = threadIdx.x;
    for (int i = t; i < 4096; i += 256) {
        int f = i >> 6, d = i & 63;
        Asm[d][f] = Amat[i];
    }
    for (int i = t; i < 4096; i += 256) {
        int sl = i >> 6, f = i & 63;
        Ksm[sl][f] = g_K[(size_t)(b * Sq + s0 + sl) * 1024 + h * 64 + f];
    }
    __syncthreads();
    int sl = t & 63, dg = t >> 6;
    float acc[16];
    #pragma unroll
    for (int i = 0; i < 16; i++) acc[i] = 0.f;
    #pragma unroll
    for (int f4 = 0; f4 < 16; f4++) {
        float4 kv = *(const float4*)&Ksm[sl][f4*4];
        #pragma unroll
        for (int dd = 0; dd < 16; dd++) {
            float4 av = *(const float4*)&Asm[dg*16 + dd][f4*4];
            acc[dd] += kv.x*av.x + kv.y*av.y + kv.z*av.z + kv.w*av.w;
        }
    }
    #pragma unroll
    for (int dd = 0; dd < 16; dd++) {
        int d = dg * 16 + dd;
        attn[((size_t)(bh * 64 + d)) * Sq + s0 + sl] = acc[dd] * 0.125f;
    }
}

// ---------------------------------------------------------------------------
// softmax over s (2048), in place, float4.
// ---------------------------------------------------------------------------
__global__ void k_softmax(float* __restrict__ attn) {
    __shared__ float smx[8];
    __shared__ float sms[8];
    float* p = attn + (size_t)blockIdx.x * Sq;
    int t = threadIdx.x;
    float4 v0 = *(const float4*)(p + t * 8);
    float4 v1 = *(const float4*)(p + t * 8 + 4);
    float m = fmaxf(fmaxf(fmaxf(v0.x, v0.y), fmaxf(v0.z, v0.w)),
                    fmaxf(fmaxf(v1.x, v1.y), fmaxf(v1.z, v1.w)));
    #pragma unroll
    for (int o = 16; o > 0; o >>= 1) m = fmaxf(m, __shfl_xor_sync(0xffffffffu, m, o));
    if ((t & 31) == 0) smx[t >> 5] = m;
    __syncthreads();
    m = smx[0];
    #pragma unroll
    for (int i = 1; i < 8; i++) m = fmaxf(m, smx[i]);
    v0.x = __expf(v0.x - m); v0.y = __expf(v0.y - m);
    v0.z = __expf(v0.z - m); v0.w = __expf(v0.w - m);
    v1.x = __expf(v1.x - m); v1.y = __expf(v1.y - m);
    v1.z = __expf(v1.z - m); v1.w = __expf(v1.w - m);
    float l = v0.x + v0.y + v0.z + v0.w + v1.x + v1.y + v1.z + v1.w;
    #pragma unroll
    for (int o = 16; o > 0; o >>= 1) l += __shfl_xor_sync(0xffffffffu, l, o);
    if ((t & 31) == 0) sms[t >> 5] = l;
    __syncthreads();
    l = 0.f;
    #pragma unroll
    for (int i = 0; i < 8; i++) l += sms[i];
    float inv = 1.f / l;
    v0.x *= inv; v0.y *= inv; v0.z *= inv; v0.w *= inv;
    v1.x *= inv; v1.y *= inv; v1.z *= inv; v1.w *= inv;
    *(float4*)(p + t * 8)     = v0;
    *(float4*)(p + t * 8 + 4) = v1;
}

// ---------------------------------------------------------------------------
// VV[bh][d][f] += sum_{s in split} attn[bh,d,s] * V[b,s,h*64+f]   (V fp16)
// ---------------------------------------------------------------------------
__global__ void k_vv(const float* __restrict__ attn) {
    __shared__ float At[64][65];
    __shared__ float Vs[64][65];
    int split = blockIdx.x;
    int bh = blockIdx.y;
    int b = bh >> 4, h = bh & 15;
    int t = threadIdx.x;
    int tr = t >> 4, tc = t & 15;
    float acc[4][4];
    #pragma unroll
    for (int i = 0; i < 4; i++)
        #pragma unroll
        for (int j = 0; j < 4; j++) acc[i][j] = 0.f;
    int sbeg = split * 512;
    for (int sc0 = sbeg; sc0 < sbeg + 512; sc0 += 64) {
        for (int i = t; i < 4096; i += 256) {
            int d = i >> 6, ss = i & 63;
            At[d][ss] = attn[((size_t)(bh * 64 + d)) * Sq + sc0 + ss];
        }
        for (int i = t; i < 4096; i += 256) {
            int ss = i >> 6, f = i & 63;
            Vs[ss][f] = __half2float(g_Vh[(size_t)(b * Sq + sc0 + ss) * 1024 + h * 64 + f]);
        }
        __syncthreads();
        #pragma unroll 8
        for (int ss = 0; ss < 64; ss++) {
            float av[4], bv[4];
            #pragma unroll
            for (int i = 0; i < 4; i++) av[i] = At[tr * 4 + i][ss];
            #pragma unroll
            for (int j = 0; j < 4; j++) bv[j] = Vs[ss][tc * 4 + j];
            #pragma unroll
            for (int i = 0; i < 4; i++)
                #pragma unroll
                for (int j = 0; j < 4; j++) acc[i][j] += av[i] * bv[j];
        }
        __syncthreads();
    }
    #pragma unroll
    for (int i = 0; i < 4; i++)
        #pragma unroll
        for (int j = 0; j < 4; j++)
            atomicAdd(&g_VV[(size_t)bh * 4096 + (tr * 4 + i) * 64 + tc * 4 + j], acc[i][j]);
}

// ---------------------------------------------------------------------------
// stage 2 on tensor cores: scores2 = (Q@A^T)*scale via mma; fp32 softmax;
// VVV = p @ VV via mma. Block 128 threads (4 warps), 128 s-rows per block.
// ---------------------------------------------------------------------------
#define S2_SSM  0                         // 128*65*4 = 33280 (fp32 scores, pitch 65)
#define S2_LINV 33280                     // 128*4    = 512
#define S2_QH   33792                     // 128*72*2 = 18432 (Q fp16 -> reused as P fp16)
#define S2_AH   52224                     // 64*72*2  = 9216  (A fp16, [d][f])
#define S2_VT   61440                     // 64*72*2  = 9216  (VV^T fp16, [f][d])
#define S2_SMEM 70656

__global__ void __launch_bounds__(128) k_stage2(const float* __restrict__ Amat) {
    extern __shared__ char smem[];
    uint32_t sb = smem_u32(smem);
    float* Ssm  = (float*)(smem + S2_SSM);
    float* Linv = (float*)(smem + S2_LINV);
    __half* Qh  = (__half*)(smem + S2_QH);    // later reused for P
    __half* Ah  = (__half*)(smem + S2_AH);
    __half* Vt  = (__half*)(smem + S2_VT);
    int bh = blockIdx.y;
    int b = bh >> 4, h = bh & 15;
    int s0 = blockIdx.x * 128;
    int t = threadIdx.x, lane = t & 31, w = t >> 5;

    for (int i = t; i < 8192; i += 128) {           // Q tile 128x64 -> fp16
        int r = i >> 6, f = i & 63;
        Qh[r*72 + f] = __float2half(g_Q[(size_t)(b * Sq + s0 + r) * 1024 + h * 64 + f]);
    }
    for (int i = t; i < 4096; i += 128) {           // A [d][f] fp16; VV^T [f][d] fp16
        int d = i >> 6, f = i & 63;
        Ah[d*72 + f] = __float2half(Amat[i]);
        Vt[f*72 + d] = __float2half(g_VV[(size_t)bh * 4096 + i]);
    }
    __syncthreads();

    int aRow = lane & 15, aKo = (lane >> 4) << 3;
    int bRow = (lane & 7) + ((lane >> 4) << 3);
    int bKo = ((lane >> 3) & 1) << 3;

    // ---- pass 1: scores2 = Q @ A^T (rows s, cols d), K = f = 64 ----
    {
        float acc[2][8][4];
        #pragma unroll
        for (int i = 0; i < 2; i++)
            #pragma unroll
            for (int j = 0; j < 8; j++)
                #pragma unroll
                for (int k = 0; k < 4; k++) acc[i][j][k] = 0.f;
        #pragma unroll
        for (int ks = 0; ks < 4; ks++) {
            uint32_t aq[2][4], bf[8][2];
            #pragma unroll
            for (int mt = 0; mt < 2; mt++)
                ldsm4(aq[mt], sb + S2_QH +
                      (uint32_t)((w*32 + mt*16 + aRow) * 72 + ks*16 + aKo) * 2);
            #pragma unroll
            for (int g = 0; g < 4; g++) {
                uint32_t r[4];
                ldsm4(r, sb + S2_AH + (uint32_t)((g*16 + bRow) * 72 + ks*16 + bKo) * 2);
                bf[g*2][0] = r[0]; bf[g*2][1] = r[1];
                bf[g*2+1][0] = r[2]; bf[g*2+1][1] = r[3];
            }
            #pragma unroll
            for (int mt = 0; mt < 2; mt++)
                #pragma unroll
                for (int nt = 0; nt < 8; nt++) mma16816(acc[mt][nt], aq[mt], bf[nt]);
        }
        #pragma unroll
        for (int mt = 0; mt < 2; mt++) {
            int r0 = w*32 + mt*16 + (lane >> 2);
            #pragma unroll
            for (int nt = 0; nt < 8; nt++) {
                int c = nt*8 + (lane & 3) * 2;
                Ssm[r0*65 + c]       = acc[mt][nt][0] * 0.125f;
                Ssm[r0*65 + c + 1]   = acc[mt][nt][1] * 0.125f;
                Ssm[(r0+8)*65 + c]   = acc[mt][nt][2] * 0.125f;
                Ssm[(r0+8)*65 + c+1] = acc[mt][nt][3] * 0.125f;
            }
        }
    }
    __syncthreads();

    // ---- fp32 softmax over d for row t; write P fp16 (reusing Qh) ----
    {
        float sc[64];
        float m = -1e30f;
        #pragma unroll
        for (int d = 0; d < 64; d++) { sc[d] = Ssm[t*65 + d]; m = fmaxf(m, sc[d]); }
        float l = 0.f;
        #pragma unroll
        for (int d = 0; d < 64; d++) { float e = __expf(sc[d] - m); sc[d] = e; l += e; }
        Linv[t] = 1.f / l;
        #pragma unroll
        for (int d = 0; d < 64; d++) Qh[t*72 + d] = __float2half(sc[d]);
    }
    __syncthreads();

    // ---- pass 2: out = P @ VV (rows s, cols f), K = d = 64; B = VV^T ----
    {
        float acc[2][8][4];
        #pragma unroll
        for (int i = 0; i < 2; i++)
            #pragma unroll
            for (int j = 0; j < 8; j++)
                #pragma unroll
                for (int k = 0; k < 4; k++) acc[i][j][k] = 0.f;
        #pragma unroll
        for (int ks = 0; ks < 4; ks++) {
            uint32_t aq[2][4], bf[8][2];
            #pragma unroll
            for (int mt = 0; mt < 2; mt++)
                ldsm4(aq[mt], sb + S2_QH +
                      (uint32_t)((w*32 + mt*16 + aRow) * 72 + ks*16 + aKo) * 2);
            #pragma unroll
            for (int g = 0; g < 4; g++) {
                uint32_t r[4];
                ldsm4(r, sb + S2_VT + (uint32_t)((g*16 + bRow) * 72 + ks*16 + bKo) * 2);
                bf[g*2][0] = r[0]; bf[g*2][1] = r[1];
                bf[g*2+1][0] = r[2]; bf[g*2+1][1] = r[3];
            }
            #pragma unroll
            for (int mt = 0; mt < 2; mt++)
                #pragma unroll
                for (int nt = 0; nt < 8; nt++) mma16816(acc[mt][nt], aq[mt], bf[nt]);
        }
        #pragma unroll
        for (int mt = 0; mt < 2; mt++) {
            int r0 = w*32 + mt*16 + (lane >> 2);
            float inv0 = Linv[r0], inv1 = Linv[r0 + 8];
            float* O0 = g_VVV + ((size_t)bh * Sq + s0 + r0) * 64;
            float* O1 = g_VVV + ((size_t)bh * Sq + s0 + r0 + 8) * 64;
            #pragma unroll
            for (int nt = 0; nt < 8; nt++) {
                int c = nt*8 + (lane & 3) * 2;
                *(float2*)(O0 + c) = make_float2(acc[mt][nt][0] * inv0, acc[mt][nt][1] * inv0);
                *(float2*)(O1 + c) = make_float2(acc[mt][nt][2] * inv1, acc[mt][nt][3] * inv1);
            }
        }
    }
}

// ---------------------------------------------------------------------------
// LayerNorm over last dim (1024), x = in1 + res.
// sel=0: in1=g_VVV, res=Xq, out=g_O1, ALSO emits fp16 to g_Ah.
// sel=1: in1=g_O2,  res=g_O1, out=d_out.
// ---------------------------------------------------------------------------
__global__ void k_ln(const float* __restrict__ rese, const float* __restrict__ g,
                     const float* __restrict__ bb, float* __restrict__ oute, int sel) {
    const float* in1 = sel ? g_O2 : g_VVV;
    const float* res = sel ? g_O1 : rese;
    float* out = sel ? oute : g_O1;
    __shared__ float sm1[8];
    __shared__ float sm2[8];
    size_t base = (size_t)blockIdx.x * 1024;
    int t = threadIdx.x;
    float v[4];
    float sum = 0.f;
    #pragma unroll
    for (int i = 0; i < 4; i++) {
        int c = t + i * 256;
        v[i] = in1[base + c] + res[base + c];
        sum += v[i];
    }
    #pragma unroll
    for (int o = 16; o > 0; o >>= 1) sum += __shfl_xor_sync(0xffffffffu, sum, o);
    if ((t & 31) == 0) sm1[t >> 5] = sum;
    __syncthreads();
    sum = 0.f;
    #pragma unroll
    for (int i = 0; i < 8; i++) sum += sm1[i];
    float mean = sum * (1.f / 1024.f);
    float sq = 0.f;
    #pragma unroll
    for (int i = 0; i < 4; i++) { float d = v[i] - mean; sq += d * d; }
    #pragma unroll
    for (int o = 16; o > 0; o >>= 1) sq += __shfl_xor_sync(0xffffffffu, sq, o);
    if ((t & 31) == 0) sm2[t >> 5] = sq;
    __syncthreads();
    sq = 0.f;
    #pragma unroll
    for (int i = 0; i < 8; i++) sq += sm2[i];
    float rstd = rsqrtf(sq * (1.f / 1024.f) + 1e-5f);
    #pragma unroll
    for (int i = 0; i < 4; i++) {
        int c = t + i * 256;
        float o = (v[i] - mean) * rstd * g[c] + bb[c];
        out[base + c] = o;
        if (sel == 0) g_Ah[base + c] = __float2half(o);
    }
}

// ===========================================================================
// Host side — single stream.
// ===========================================================================
extern "C" void kernel_launch(void* const* d_in, const int* in_sizes, int n_in,
                              void* d_out, int out_size) {
    const float* Xq  = (const float*)d_in[0];
    const float* Xk  = (const float*)d_in[1];
    const float* Xv  = (const float*)d_in[2];
    const float* Wq1 = (const float*)d_in[3];
    const float* Wq2 = (const float*)d_in[4];
    const float* Wk1 = (const float*)d_in[5];
    const float* Wk2 = (const float*)d_in[6];
    const float* Wv  = (const float*)d_in[7];
    const float* Wfc = (const float*)d_in[8];
    const float* Am  = (const float*)d_in[9];
    const float* lng = (const float*)d_in[10];
    const float* lnb = (const float*)d_in[11];
    float* out = (float*)d_out;
    size_t attn_off = (out_size > OUT_MAIN) ? (size_t)(out_size - OUT_MAIN) : 0;
    float* attn = out + attn_off;

    void *pO2, *pVV;
    cudaGetSymbolAddress(&pO2, g_O2);
    cudaGetSymbolAddress(&pVV, g_VV);

    cudaFuncSetAttribute(k_hgemm, cudaFuncAttributeMaxDynamicSharedMemorySize, HG_SMEM);
    cudaFuncSetAttribute(k_stage2, cudaFuncAttributeMaxDynamicSharedMemorySize, S2_SMEM);

    k_proj1<<<512, 256>>>(Xq, Wq1, 0);
    k_proj1<<<512, 256>>>(Xk, Wk1, 1);
    k_proj2<<<dim3(8, 256), 256>>>(Wq2, 0);
    k_proj2<<<dim3(8, 256), 256>>>(Wk2, 1);

    // V = Xv @ Wv on tensor cores (fp16), output fp16 g_Vh
    k_half<<<16384, 256>>>(Xv);
    k_halfT<<<dim3(32, 32), dim3(32, 8)>>>(Wv, 0);
    k_hgemm<<<dim3(8, 128), 512, HG_SMEM>>>(nullptr, 0);

    k_scores<<<dim3(32, 128), 256>>>(Am, attn);
    k_softmax<<<8192, 256>>>(attn);
    cudaMemsetAsync(pVV, 0, (size_t)BHn * DHq * DHq * sizeof(float));
    k_vv<<<dim3(4, 128), 256>>>(attn);
    k_stage2<<<dim3(16, 128), 128, S2_SMEM>>>(Am);
    k_ln<<<16384, 256>>>(Xq, lng, lnb, nullptr, 0);      // out1 = LN(VVV+Xq) + fp16

    // out2 = out1 @ Wfc on tensor cores (fp16)
    k_halfT<<<dim3(32, 32), dim3(32, 8)>>>(Wfc, 1);
    k_hgemm<<<dim3(8, 128), 512, HG_SMEM>>>((float*)pO2, 1);

    k_ln<<<16384, 256>>>(nullptr, lng, lnb, out, 1);     // out = LN(out2 + out1)
}

// round 9
// speedup vs baseline: 1.2145x; 1.0680x over previous
#include <cuda_runtime.h>
#include <cuda_fp16.h>
#include <cstdint>

// Problem constants
#define Bq   8
#define Sq   2048
#define Dq   1024
#define Hq   16
#define DHq  64
#define Mrows (Bq*Sq)        // 16384
#define BHn   (Bq*Hq)        // 128
#define OUT_MAIN (Mrows*Dq)  // 16777216 floats of `outputs`

__device__ float g_Tq[Mrows*32];
__device__ float g_Tk[Mrows*32];
__device__ float g_K [Mrows*Dq];
__device__ float g_VV[BHn*DHq*DHq];
__device__ float g_VVV[Mrows*Dq];
__device__ float g_O1[Mrows*Dq];
__device__ float g_O2[Mrows*Dq];
__device__ float g_L [BHn*DHq];                     // softmax row sums (stage 1)

// fp16 buffers
__device__ __align__(128) __half g_Ah [Mrows*Dq];   // A operand of hgemm
__device__ __align__(128) __half g_Vh [Mrows*Dq];   // V in fp16 (hgemm1 output)
__device__ __align__(128) __half g_Qh [Mrows*Dq];   // Q in fp16 (proj2 output)
__device__ __align__(128) __half g_Bh [Dq*Dq];      // transposed Wv  [n][k]
__device__ __align__(128) __half g_Bh2[Dq*Dq];      // transposed Wfc [n][k]

// ===========================================================================
// PTX helpers (sm_80/90 baseline — compile under compute_103)
// ===========================================================================
__device__ __forceinline__ uint32_t smem_u32(const void* p) {
    uint32_t a;
    asm("{ .reg .u64 t; cvta.to.shared.u64 t, %1; cvt.u32.u64 %0, t; }" : "=r"(a) : "l"(p));
    return a;
}
__device__ __forceinline__ void cpa16(uint32_t s, const void* g) {
    asm volatile("cp.async.cg.shared.global [%0], [%1], 16;" :: "r"(s), "l"(g));
}
__device__ __forceinline__ void cpa_commit() {
    asm volatile("cp.async.commit_group;" ::: "memory");
}
__device__ __forceinline__ void cpa_wait1() {
    asm volatile("cp.async.wait_group 1;" ::: "memory");
}
__device__ __forceinline__ void ldsm4(uint32_t* r, uint32_t addr) {
    asm volatile("ldmatrix.sync.aligned.m8n8.x4.shared.b16 {%0,%1,%2,%3}, [%4];"
                 : "=r"(r[0]), "=r"(r[1]), "=r"(r[2]), "=r"(r[3]) : "r"(addr));
}
__device__ __forceinline__ void mma16816(float* c, const uint32_t* a, const uint32_t* b) {
    asm volatile(
        "mma.sync.aligned.m16n8k16.row.col.f32.f16.f16.f32 "
        "{%0,%1,%2,%3}, {%4,%5,%6,%7}, {%8,%9}, {%0,%1,%2,%3};"
        : "+f"(c[0]), "+f"(c[1]), "+f"(c[2]), "+f"(c[3])
        : "r"(a[0]), "r"(a[1]), "r"(a[2]), "r"(a[3]), "r"(b[0]), "r"(b[1]));
}

// ===========================================================================
// HMMA GEMM: C = A @ W (fp16 x1), 512 threads, 16 warps of 32x32, K-chunk 64.
// sel=0: B=g_Bh, output fp16 -> g_Vh.  sel=1: B=g_Bh2, output fp32 -> C.
// ===========================================================================
#define GP 72
#define ST_AH 0
#define ST_BH 18432
#define ST_BYTES 36864
#define HG_SMEM (2*ST_BYTES)

__device__ __forceinline__ void hg_load_stage(uint32_t sb, int st, const __half* gB,
                                              int m0, int n0, int kc, int tid) {
    uint32_t base = sb + st * ST_BYTES;
    #pragma unroll
    for (int i = 0; i < 2; i++) {
        int idx = tid + i * 512;
        int row = idx >> 3, c8 = idx & 7;
        uint32_t so = (uint32_t)(row * GP + c8 * 8) * 2;
        cpa16(base + ST_AH + so, g_Ah + (size_t)(m0 + row) * Dq + kc + c8 * 8);
        cpa16(base + ST_BH + so, gB   + (size_t)(n0 + row) * Dq + kc + c8 * 8);
    }
}

__global__ void __launch_bounds__(512) k_hgemm(float* __restrict__ C, int sel) {
    extern __shared__ char smem[];
    uint32_t sb = smem_u32(smem);
    const __half* gB = sel ? g_Bh2 : g_Bh;
    int tid = threadIdx.x;
    int lane = tid & 31, w = tid >> 5;
    int wm = w & 3, wn = w >> 2;
    int m0 = blockIdx.y * 128;
    int n0 = blockIdx.x * 128;

    float acc[2][4][4];
    #pragma unroll
    for (int i = 0; i < 2; i++)
        #pragma unroll
        for (int j = 0; j < 4; j++)
            #pragma unroll
            for (int k = 0; k < 4; k++) acc[i][j][k] = 0.f;

    hg_load_stage(sb, 0, gB, m0, n0, 0, tid);
    cpa_commit();
    hg_load_stage(sb, 1, gB, m0, n0, 64, tid);
    cpa_commit();
    cpa_wait1();
    __syncthreads();

    int aRow = lane & 15, aKo = (lane >> 4) << 3;
    int bRow = (lane & 7) + ((lane >> 4) << 3);
    int bKo = ((lane >> 3) & 1) << 3;

    for (int c = 0; c < 16; c++) {
        int st = c & 1;
        uint32_t s0 = sb + st * ST_BYTES;
        #pragma unroll
        for (int kh = 0; kh < 4; kh++) {
            uint32_t ah[2][4], bh[4][2];
            #pragma unroll
            for (int mt = 0; mt < 2; mt++) {
                uint32_t off = (uint32_t)((wm * 32 + mt * 16 + aRow) * GP + kh * 16 + aKo) * 2;
                ldsm4(ah[mt], s0 + ST_AH + off);
            }
            #pragma unroll
            for (int nt2 = 0; nt2 < 2; nt2++) {
                uint32_t off = (uint32_t)((wn * 32 + nt2 * 16 + bRow) * GP + kh * 16 + bKo) * 2;
                uint32_t r[4];
                ldsm4(r, s0 + ST_BH + off);
                bh[nt2*2][0] = r[0]; bh[nt2*2][1] = r[1];
                bh[nt2*2+1][0] = r[2]; bh[nt2*2+1][1] = r[3];
            }
            #pragma unroll
            for (int mt = 0; mt < 2; mt++)
                #pragma unroll
                for (int nt = 0; nt < 4; nt++) mma16816(acc[mt][nt], ah[mt], bh[nt]);
        }
        __syncthreads();
        if (c + 2 < 16)
            hg_load_stage(sb, st, gB, m0, n0, (c + 2) * 64, tid);
        cpa_commit();
        cpa_wait1();
        __syncthreads();
    }

    if (sel == 0) {
        #pragma unroll
        for (int mt = 0; mt < 2; mt++) {
            int r0 = m0 + wm * 32 + mt * 16 + (lane >> 2);
            #pragma unroll
            for (int nt = 0; nt < 4; nt++) {
                int col = n0 + wn * 32 + nt * 8 + (lane & 3) * 2;
                *(__half2*)(g_Vh + (size_t)r0 * Dq + col) =
                    __floats2half2_rn(acc[mt][nt][0], acc[mt][nt][1]);
                *(__half2*)(g_Vh + (size_t)(r0 + 8) * Dq + col) =
                    __floats2half2_rn(acc[mt][nt][2], acc[mt][nt][3]);
            }
        }
    } else {
        #pragma unroll
        for (int mt = 0; mt < 2; mt++) {
            int r0 = m0 + wm * 32 + mt * 16 + (lane >> 2);
            #pragma unroll
            for (int nt = 0; nt < 4; nt++) {
                int col = n0 + wn * 32 + nt * 8 + (lane & 3) * 2;
                *(float2*)(C + (size_t)r0 * Dq + col)       = make_float2(acc[mt][nt][0], acc[mt][nt][1]);
                *(float2*)(C + (size_t)(r0 + 8) * Dq + col) = make_float2(acc[mt][nt][2], acc[mt][nt][3]);
            }
        }
    }
}

// ===========================================================================
// fp32 -> fp16 convert into g_Ah
// ===========================================================================
__global__ void k_half(const float* __restrict__ x) {
    size_t i = ((size_t)blockIdx.x * 256 + threadIdx.x) * 4;
    float4 v = *(const float4*)(x + i);
    *(__half2*)(g_Ah + i)     = __floats2half2_rn(v.x, v.y);
    *(__half2*)(g_Ah + i + 2) = __floats2half2_rn(v.z, v.w);
}

// ===========================================================================
// fp32 W[k][n] -> transposed fp16 Wt[n][k], sel picks g_Bh / g_Bh2
// ===========================================================================
__global__ void k_halfT(const float* __restrict__ W, int sel) {
    __shared__ float t[32][33];
    __half* dst = sel ? g_Bh2 : g_Bh;
    int tx = threadIdx.x, ty = threadIdx.y;
    int bx = blockIdx.x, by = blockIdx.y;
    #pragma unroll
    for (int i = 0; i < 4; i++)
        t[ty + i*8][tx] = W[(size_t)(by*32 + ty + i*8) * Dq + bx*32 + tx];
    __syncthreads();
    #pragma unroll
    for (int i = 0; i < 4; i++) {
        size_t o = (size_t)(bx*32 + ty + i*8) * Dq + by*32 + tx;
        dst[o] = __float2half(t[tx][ty + i*8]);
    }
}

// ---------------------------------------------------------------------------
// proj1: T = X @ W1.  32 rows/block (512 blocks), k-chunk 64, 4 acc/thread.
// ---------------------------------------------------------------------------
__global__ void k_proj1(const float* __restrict__ X, const float* __restrict__ W, int sel) {
    __shared__ float Xs[32][64];
    __shared__ float Ws[64][32];
    float* T = sel ? g_Tk : g_Tq;
    int t = threadIdx.x;
    int row0 = blockIdx.x * 32;
    int tr = t >> 5, tc = t & 31;
    float acc[4] = {0.f, 0.f, 0.f, 0.f};
    for (int kc = 0; kc < 1024; kc += 64) {
        #pragma unroll
        for (int i = 0; i < 2; i++) {
            int idx = t + i * 256;
            int r = idx >> 4, c4 = idx & 15;
            *(float4*)&Xs[r][c4*4] = *(const float4*)(X + (size_t)(row0 + r) * 1024 + kc + c4*4);
        }
        #pragma unroll
        for (int i = 0; i < 2; i++) {
            int idx = t + i * 256;
            int k = idx >> 3, c = (idx & 7) * 4;
            *(float4*)&Ws[k][c] = *(const float4*)(W + (size_t)(kc + k) * 32 + c);
        }
        __syncthreads();
        #pragma unroll
        for (int k = 0; k < 64; k += 4) {
            float w0 = Ws[k][tc], w1 = Ws[k+1][tc], w2 = Ws[k+2][tc], w3 = Ws[k+3][tc];
            #pragma unroll
            for (int i = 0; i < 4; i++) {
                float4 x = *(const float4*)&Xs[tr*4 + i][k];
                acc[i] += x.x*w0 + x.y*w1 + x.z*w2 + x.w*w3;
            }
        }
        __syncthreads();
    }
    #pragma unroll
    for (int i = 0; i < 4; i++)
        T[(size_t)(row0 + tr*4 + i) * 32 + tc] = acc[i];
}

// ---------------------------------------------------------------------------
// proj2: O = T @ W2   (T: [16384,32], W2: [32,1024])
// sel=0: output fp16 -> g_Qh.  sel=1: output fp32 -> g_K.
// ---------------------------------------------------------------------------
__global__ void k_proj2(const float* __restrict__ W2, int sel) {
    __shared__ float Ts[64][33];
    __shared__ float Ws[32][132];
    const float* T = sel ? g_Tk : g_Tq;
    int t = threadIdx.x;
    int row0 = blockIdx.y * 64;
    int n0 = blockIdx.x * 128;
    #pragma unroll
    for (int i = 0; i < 2; i++) {
        int idx = (t + i * 256) * 4;
        int r = idx >> 5, k = idx & 31;
        float4 v = *(const float4*)(T + (size_t)(row0 + r) * 32 + k);
        Ts[r][k] = v.x; Ts[r][k+1] = v.y; Ts[r][k+2] = v.z; Ts[r][k+3] = v.w;
    }
    #pragma unroll
    for (int i = 0; i < 4; i++) {
        int idx = (t + i * 256) * 4;
        int k = idx >> 7, c = idx & 127;
        *(float4*)&Ws[k][c] = *(const float4*)(W2 + (size_t)k * 1024 + n0 + c);
    }
    __syncthreads();
    int tr = t >> 5, tc = t & 31;
    float acc[8][4];
    #pragma unroll
    for (int i = 0; i < 8; i++)
        #pragma unroll
        for (int j = 0; j < 4; j++) acc[i][j] = 0.f;
    #pragma unroll
    for (int k = 0; k < 32; k++) {
        float4 wv = *(const float4*)&Ws[k][tc*4];
        #pragma unroll
        for (int i = 0; i < 8; i++) {
            float tv = Ts[tr*8 + i][k];
            acc[i][0] += tv * wv.x;
            acc[i][1] += tv * wv.y;
            acc[i][2] += tv * wv.z;
            acc[i][3] += tv * wv.w;
        }
    }
    if (sel == 0) {
        #pragma unroll
        for (int i = 0; i < 8; i++) {
            size_t off = (size_t)(row0 + tr*8 + i) * 1024 + n0 + tc*4;
            *(__half2*)(g_Qh + off)     = __floats2half2_rn(acc[i][0], acc[i][1]);
            *(__half2*)(g_Qh + off + 2) = __floats2half2_rn(acc[i][2], acc[i][3]);
        }
    } else {
        #pragma unroll
        for (int i = 0; i < 8; i++)
            *(float4*)(g_K + (size_t)(row0 + tr*8 + i) * 1024 + n0 + tc*4) =
                make_float4(acc[i][0], acc[i][1], acc[i][2], acc[i][3]);
    }
}

// ---------------------------------------------------------------------------
// scores+exp fused: E[bh,d,s] = exp(scale * sum_f A[f,d] K[b,h,s,f])  (raw exp,
// no max subtraction — |S| <~ 1 by construction). Partial row sums -> g_L.
// ---------------------------------------------------------------------------
__global__ void k_scores_exp(const float* __restrict__ Amat, float* __restrict__ attn) {
    __shared__ float Asm[64][68];
    __shared__ float Ksm[64][68];
    __shared__ float wsum[8][16];
    int bh = blockIdx.y;
    int b = bh >> 4, h = bh & 15;
    int s0 = blockIdx.x * 64;
    int t = threadIdx.x;
    for (int i = t; i < 4096; i += 256) {
        int f = i >> 6, d = i & 63;
        Asm[d][f] = Amat[i];
    }
    for (int i = t; i < 4096; i += 256) {
        int sl = i >> 6, f = i & 63;
        Ksm[sl][f] = g_K[(size_t)(b * Sq + s0 + sl) * 1024 + h * 64 + f];
    }
    __syncthreads();
    int sl = t & 63, dg = t >> 6;
    float acc[16];
    #pragma unroll
    for (int i = 0; i < 16; i++) acc[i] = 0.f;
    #pragma unroll
    for (int f4 = 0; f4 < 16; f4++) {
        float4 kv = *(const float4*)&Ksm[sl][f4*4];
        #pragma unroll
        for (int dd = 0; dd < 16; dd++) {
            float4 av = *(const float4*)&Asm[dg*16 + dd][f4*4];
            acc[dd] += kv.x*av.x + kv.y*av.y + kv.z*av.z + kv.w*av.w;
        }
    }
    float es[16];
    #pragma unroll
    for (int dd = 0; dd < 16; dd++) {
        float e = __expf(acc[dd] * 0.125f);
        es[dd] = e;
        attn[((size_t)(bh * 64 + dg*16 + dd)) * Sq + s0 + sl] = e;
    }
    #pragma unroll
    for (int dd = 0; dd < 16; dd++) {
        float v = es[dd];
        #pragma unroll
        for (int o = 16; o > 0; o >>= 1) v += __shfl_xor_sync(0xffffffffu, v, o);
        if ((t & 31) == 0) wsum[t >> 5][dd] = v;
    }
    __syncthreads();
    if (t < 64) {
        int dgg = t >> 4, dd = t & 15;
        float s = wsum[dgg*2][dd] + wsum[dgg*2 + 1][dd];
        atomicAdd(&g_L[bh*64 + dgg*16 + dd], s);
    }
}

// ---------------------------------------------------------------------------
// vv: normalizes attn in place (E *= 1/l) and accumulates normalized
// VV[bh][d][f] += sum_s attn_n[bh,d,s] * V[b,s,h*64+f]   (V fp16)
// ---------------------------------------------------------------------------
__global__ void k_vv(float* __restrict__ attn) {
    __shared__ float At[64][65];
    __shared__ float Vs[64][65];
    __shared__ float inv[64];
    int split = blockIdx.x;
    int bh = blockIdx.y;
    int b = bh >> 4, h = bh & 15;
    int t = threadIdx.x;
    int tr = t >> 4, tc = t & 15;
    if (t < 64) inv[t] = 1.f / g_L[bh*64 + t];
    __syncthreads();
    float acc[4][4];
    #pragma unroll
    for (int i = 0; i < 4; i++)
        #pragma unroll
        for (int j = 0; j < 4; j++) acc[i][j] = 0.f;
    int sbeg = split * 512;
    for (int sc0 = sbeg; sc0 < sbeg + 512; sc0 += 64) {
        for (int i = t; i < 4096; i += 256) {
            int d = i >> 6, ss = i & 63;
            size_t idx = ((size_t)(bh * 64 + d)) * Sq + sc0 + ss;
            float en = attn[idx] * inv[d];
            At[d][ss] = en;
            attn[idx] = en;
        }
        for (int i = t; i < 4096; i += 256) {
            int ss = i >> 6, f = i & 63;
            Vs[ss][f] = __half2float(g_Vh[(size_t)(b * Sq + sc0 + ss) * 1024 + h * 64 + f]);
        }
        __syncthreads();
        #pragma unroll 8
        for (int ss = 0; ss < 64; ss++) {
            float av[4], bv[4];
            #pragma unroll
            for (int i = 0; i < 4; i++) av[i] = At[tr * 4 + i][ss];
            #pragma unroll
            for (int j = 0; j < 4; j++) bv[j] = Vs[ss][tc * 4 + j];
            #pragma unroll
            for (int i = 0; i < 4; i++)
                #pragma unroll
                for (int j = 0; j < 4; j++) acc[i][j] += av[i] * bv[j];
        }
        __syncthreads();
    }
    #pragma unroll
    for (int i = 0; i < 4; i++)
        #pragma unroll
        for (int j = 0; j < 4; j++)
            atomicAdd(&g_VV[(size_t)bh * 4096 + (tr * 4 + i) * 64 + tc * 4 + j], acc[i][j]);
}

// ---------------------------------------------------------------------------
// stage 2 on tensor cores: scores2 = (Q@A^T)*scale via mma; fp32 softmax;
// VVV = p @ VV via mma. Block 128 threads (4 warps), 128 s-rows per block.
// ---------------------------------------------------------------------------
#define S2_SSM  0                         // 128*65*4 = 33280
#define S2_LINV 33280                     // 128*4    = 512
#define S2_QH   33792                     // 128*72*2 = 18432 (Q fp16 -> reused as P)
#define S2_AH   52224                     // 64*72*2  = 9216  (A fp16, [d][f])
#define S2_VT   61440                     // 64*72*2  = 9216  (VV^T fp16, [f][d])
#define S2_SMEM 70656

__global__ void __launch_bounds__(128) k_stage2(const float* __restrict__ Amat) {
    extern __shared__ char smem[];
    uint32_t sb = smem_u32(smem);
    float* Ssm  = (float*)(smem + S2_SSM);
    float* Linv = (float*)(smem + S2_LINV);
    __half* Qh  = (__half*)(smem + S2_QH);
    __half* Ah  = (__half*)(smem + S2_AH);
    __half* Vt  = (__half*)(smem + S2_VT);
    int bh = blockIdx.y;
    int b = bh >> 4, h = bh & 15;
    int s0 = blockIdx.x * 128;
    int t = threadIdx.x, lane = t & 31, w = t >> 5;

    for (int i = t; i < 1024; i += 128) {            // Q tile 128x64 fp16, 16B chunks
        int r = i >> 3, c8 = (i & 7) * 8;
        *(uint4*)((char*)smem + S2_QH + (uint32_t)(r*72 + c8) * 2) =
            *(const uint4*)(g_Qh + (size_t)(b * Sq + s0 + r) * 1024 + h * 64 + c8);
    }
    for (int i = t; i < 4096; i += 128) {            // A [d][f]; VV^T [f][d] fp16
        int d = i >> 6, f = i & 63;
        Ah[d*72 + f] = __float2half(Amat[i]);
        Vt[f*72 + d] = __float2half(g_VV[(size_t)bh * 4096 + i]);
    }
    __syncthreads();

    int aRow = lane & 15, aKo = (lane >> 4) << 3;
    int bRow = (lane & 7) + ((lane >> 4) << 3);
    int bKo = ((lane >> 3) & 1) << 3;

    // ---- pass 1: scores2 = Q @ A^T ----
    {
        float acc[2][8][4];
        #pragma unroll
        for (int i = 0; i < 2; i++)
            #pragma unroll
            for (int j = 0; j < 8; j++)
                #pragma unroll
                for (int k = 0; k < 4; k++) acc[i][j][k] = 0.f;
        #pragma unroll
        for (int ks = 0; ks < 4; ks++) {
            uint32_t aq[2][4], bf[8][2];
            #pragma unroll
            for (int mt = 0; mt < 2; mt++)
                ldsm4(aq[mt], sb + S2_QH +
                      (uint32_t)((w*32 + mt*16 + aRow) * 72 + ks*16 + aKo) * 2);
            #pragma unroll
            for (int g = 0; g < 4; g++) {
                uint32_t r[4];
                ldsm4(r, sb + S2_AH + (uint32_t)((g*16 + bRow) * 72 + ks*16 + bKo) * 2);
                bf[g*2][0] = r[0]; bf[g*2][1] = r[1];
                bf[g*2+1][0] = r[2]; bf[g*2+1][1] = r[3];
            }
            #pragma unroll
            for (int mt = 0; mt < 2; mt++)
                #pragma unroll
                for (int nt = 0; nt < 8; nt++) mma16816(acc[mt][nt], aq[mt], bf[nt]);
        }
        #pragma unroll
        for (int mt = 0; mt < 2; mt++) {
            int r0 = w*32 + mt*16 + (lane >> 2);
            #pragma unroll
            for (int nt = 0; nt < 8; nt++) {
                int c = nt*8 + (lane & 3) * 2;
                Ssm[r0*65 + c]       = acc[mt][nt][0] * 0.125f;
                Ssm[r0*65 + c + 1]   = acc[mt][nt][1] * 0.125f;
                Ssm[(r0+8)*65 + c]   = acc[mt][nt][2] * 0.125f;
                Ssm[(r0+8)*65 + c+1] = acc[mt][nt][3] * 0.125f;
            }
        }
    }
    __syncthreads();

    // ---- fp32 softmax over d; write P fp16 (reuse Qh) ----
    {
        float sc[64];
        float m = -1e30f;
        #pragma unroll
        for (int d = 0; d < 64; d++) { sc[d] = Ssm[t*65 + d]; m = fmaxf(m, sc[d]); }
        float l = 0.f;
        #pragma unroll
        for (int d = 0; d < 64; d++) { float e = __expf(sc[d] - m); sc[d] = e; l += e; }
        Linv[t] = 1.f / l;
        #pragma unroll
        for (int d = 0; d < 64; d++) Qh[t*72 + d] = __float2half(sc[d]);
    }
    __syncthreads();

    // ---- pass 2: out = P @ VV ----
    {
        float acc[2][8][4];
        #pragma unroll
        for (int i = 0; i < 2; i++)
            #pragma unroll
            for (int j = 0; j < 8; j++)
                #pragma unroll
                for (int k = 0; k < 4; k++) acc[i][j][k] = 0.f;
        #pragma unroll
        for (int ks = 0; ks < 4; ks++) {
            uint32_t aq[2][4], bf[8][2];
            #pragma unroll
            for (int mt = 0; mt < 2; mt++)
                ldsm4(aq[mt], sb + S2_QH +
                      (uint32_t)((w*32 + mt*16 + aRow) * 72 + ks*16 + aKo) * 2);
            #pragma unroll
            for (int g = 0; g < 4; g++) {
                uint32_t r[4];
                ldsm4(r, sb + S2_VT + (uint32_t)((g*16 + bRow) * 72 + ks*16 + bKo) * 2);
                bf[g*2][0] = r[0]; bf[g*2][1] = r[1];
                bf[g*2+1][0] = r[2]; bf[g*2+1][1] = r[3];
            }
            #pragma unroll
            for (int mt = 0; mt < 2; mt++)
                #pragma unroll
                for (int nt = 0; nt < 8; nt++) mma16816(acc[mt][nt], aq[mt], bf[nt]);
        }
        #pragma unroll
        for (int mt = 0; mt < 2; mt++) {
            int r0 = w*32 + mt*16 + (lane >> 2);
            float inv0 = Linv[r0], inv1 = Linv[r0 + 8];
            float* O0 = g_VVV + ((size_t)bh * Sq + s0 + r0) * 64;
            float* O1 = g_VVV + ((size_t)bh * Sq + s0 + r0 + 8) * 64;
            #pragma unroll
            for (int nt = 0; nt < 8; nt++) {
                int c = nt*8 + (lane & 3) * 2;
                *(float2*)(O0 + c) = make_float2(acc[mt][nt][0] * inv0, acc[mt][nt][1] * inv0);
                *(float2*)(O1 + c) = make_float2(acc[mt][nt][2] * inv1, acc[mt][nt][3] * inv1);
            }
        }
    }
}

// ---------------------------------------------------------------------------
// LayerNorm over last dim (1024), x = in1 + res.
// sel=0: in1=g_VVV, res=Xq, out=g_O1, ALSO emits fp16 to g_Ah.
// sel=1: in1=g_O2,  res=g_O1, out=d_out.
// ---------------------------------------------------------------------------
__global__ void k_ln(const float* __restrict__ rese, const float* __restrict__ g,
                     const float* __restrict__ bb, float* __restrict__ oute, int sel) {
    const float* in1 = sel ? g_O2 : g_VVV;
    const float* res = sel ? g_O1 : rese;
    float* out = sel ? oute : g_O1;
    __shared__ float sm1[8];
    __shared__ float sm2[8];
    size_t base = (size_t)blockIdx.x * 1024;
    int t = threadIdx.x;
    float v[4];
    float sum = 0.f;
    #pragma unroll
    for (int i = 0; i < 4; i++) {
        int c = t + i * 256;
        v[i] = in1[base + c] + res[base + c];
        sum += v[i];
    }
    #pragma unroll
    for (int o = 16; o > 0; o >>= 1) sum += __shfl_xor_sync(0xffffffffu, sum, o);
    if ((t & 31) == 0) sm1[t >> 5] = sum;
    __syncthreads();
    sum = 0.f;
    #pragma unroll
    for (int i = 0; i < 8; i++) sum += sm1[i];
    float mean = sum * (1.f / 1024.f);
    float sq = 0.f;
    #pragma unroll
    for (int i = 0; i < 4; i++) { float d = v[i] - mean; sq += d * d; }
    #pragma unroll
    for (int o = 16; o > 0; o >>= 1) sq += __shfl_xor_sync(0xffffffffu, sq, o);
    if ((t & 31) == 0) sm2[t >> 5] = sq;
    __syncthreads();
    sq = 0.f;
    #pragma unroll
    for (int i = 0; i < 8; i++) sq += sm2[i];
    float rstd = rsqrtf(sq * (1.f / 1024.f) + 1e-5f);
    #pragma unroll
    for (int i = 0; i < 4; i++) {
        int c = t + i * 256;
        float o = (v[i] - mean) * rstd * g[c] + bb[c];
        out[base + c] = o;
        if (sel == 0) g_Ah[base + c] = __float2half(o);
    }
}

// ===========================================================================
// Host side — single stream; hgemm placed as 6th kernel launch for ncu.
// ===========================================================================
extern "C" void kernel_launch(void* const* d_in, const int* in_sizes, int n_in,
                              void* d_out, int out_size) {
    const float* Xq  = (const float*)d_in[0];
    const float* Xk  = (const float*)d_in[1];
    const float* Xv  = (const float*)d_in[2];
    const float* Wq1 = (const float*)d_in[3];
    const float* Wq2 = (const float*)d_in[4];
    const float* Wk1 = (const float*)d_in[5];
    const float* Wk2 = (const float*)d_in[6];
    const float* Wv  = (const float*)d_in[7];
    const float* Wfc = (const float*)d_in[8];
    const float* Am  = (const float*)d_in[9];
    const float* lng = (const float*)d_in[10];
    const float* lnb = (const float*)d_in[11];
    float* out = (float*)d_out;
    size_t attn_off = (out_size > OUT_MAIN) ? (size_t)(out_size - OUT_MAIN) : 0;
    float* attn = out + attn_off;

    void *pO2, *pVV, *pL;
    cudaGetSymbolAddress(&pO2, g_O2);
    cudaGetSymbolAddress(&pVV, g_VV);
    cudaGetSymbolAddress(&pL,  g_L);

    cudaFuncSetAttribute(k_hgemm, cudaFuncAttributeMaxDynamicSharedMemorySize, HG_SMEM);
    cudaFuncSetAttribute(k_stage2, cudaFuncAttributeMaxDynamicSharedMemorySize, S2_SMEM);

    // launches 1-5
    k_half<<<16384, 256>>>(Xv);
    k_halfT<<<dim3(32, 32), dim3(32, 8)>>>(Wv, 0);
    k_proj1<<<512, 256>>>(Xq, Wq1, 0);
    k_proj1<<<512, 256>>>(Xk, Wk1, 1);
    k_proj2<<<dim3(8, 256), 256>>>(Wq2, 0);           // -> g_Qh (fp16)

    // launch 6: profiled by ncu (-s 5 -c 1)
    k_hgemm<<<dim3(8, 128), 512, HG_SMEM>>>(nullptr, 0);   // V = Xv@Wv -> g_Vh

    k_proj2<<<dim3(8, 256), 256>>>(Wk2, 1);           // -> g_K (fp32)
    cudaMemsetAsync(pL,  0, (size_t)BHn * DHq * sizeof(float));
    cudaMemsetAsync(pVV, 0, (size_t)BHn * DHq * DHq * sizeof(float));
    k_scores_exp<<<dim3(32, 128), 256>>>(Am, attn);   // E + row sums
    k_vv<<<dim3(4, 128), 256>>>(attn);                // normalize attn + VV
    k_stage2<<<dim3(16, 128), 128, S2_SMEM>>>(Am);
    k_ln<<<16384, 256>>>(Xq, lng, lnb, nullptr, 0);   // out1 = LN(VVV+Xq) + fp16

    k_halfT<<<dim3(32, 32), dim3(32, 8)>>>(Wfc, 1);
    k_hgemm<<<dim3(8, 128), 512, HG_SMEM>>>((float*)pO2, 1);
    k_ln<<<16384, 256>>>(nullptr, lng, lnb, out, 1);  // out = LN(out2 + out1)
}

// round 10
// speedup vs baseline: 1.3986x; 1.1515x over previous
#include <cuda_runtime.h>
#include <cuda_fp16.h>
#include <cstdint>

// Problem constants
#define Bq   8
#define Sq   2048
#define Dq   1024
#define Hq   16
#define DHq  64
#define Mrows (Bq*Sq)        // 16384
#define BHn   (Bq*Hq)        // 128
#define OUT_MAIN (Mrows*Dq)  // 16777216 floats of `outputs`

__device__ float g_Tq[Mrows*32];
__device__ float g_Tk[Mrows*32];
__device__ float g_VV[BHn*DHq*DHq];
__device__ float g_VVV[Mrows*Dq];
__device__ float g_O1[Mrows*Dq];
__device__ float g_O2[Mrows*Dq];
__device__ float g_L [BHn*DHq];
__device__ float g_W2Aq[32*Dq];                     // per-head Wq2_h @ A^T
__device__ float g_W2Ak[32*Dq];                     // per-head Wk2_h @ A

// fp16 buffers
__device__ __align__(128) __half g_Ah [Mrows*Dq];   // A operand of hgemm
__device__ __align__(128) __half g_Vh [Mrows*Dq];   // V fp16
__device__ __align__(128) __half g_Bh [Dq*Dq];      // transposed Wv  [n][k]
__device__ __align__(128) __half g_Bh2[Dq*Dq];      // transposed Wfc [n][k]

// ===========================================================================
// PTX helpers
// ===========================================================================
__device__ __forceinline__ uint32_t smem_u32(const void* p) {
    uint32_t a;
    asm("{ .reg .u64 t; cvta.to.shared.u64 t, %1; cvt.u32.u64 %0, t; }" : "=r"(a) : "l"(p));
    return a;
}
__device__ __forceinline__ void cpa16(uint32_t s, const void* g) {
    asm volatile("cp.async.cg.shared.global [%0], [%1], 16;" :: "r"(s), "l"(g));
}
__device__ __forceinline__ void cpa_commit() {
    asm volatile("cp.async.commit_group;" ::: "memory");
}
__device__ __forceinline__ void cpa_wait1() {
    asm volatile("cp.async.wait_group 1;" ::: "memory");
}
__device__ __forceinline__ void ldsm4(uint32_t* r, uint32_t addr) {
    asm volatile("ldmatrix.sync.aligned.m8n8.x4.shared.b16 {%0,%1,%2,%3}, [%4];"
                 : "=r"(r[0]), "=r"(r[1]), "=r"(r[2]), "=r"(r[3]) : "r"(addr));
}
__device__ __forceinline__ void mma16816(float* c, const uint32_t* a, const uint32_t* b) {
    asm volatile(
        "mma.sync.aligned.m16n8k16.row.col.f32.f16.f16.f32 "
        "{%0,%1,%2,%3}, {%4,%5,%6,%7}, {%8,%9}, {%0,%1,%2,%3};"
        : "+f"(c[0]), "+f"(c[1]), "+f"(c[2]), "+f"(c[3])
        : "r"(a[0]), "r"(a[1]), "r"(a[2]), "r"(a[3]), "r"(b[0]), "r"(b[1]));
}

// ===========================================================================
// HMMA GEMM: 512 threads, 16 warps of 32x32, K-chunk 64, 3-stage / 1 sync.
// sel=0: B=g_Bh, out fp16 -> g_Vh.  sel=1: B=g_Bh2, out fp32 -> C.
// ===========================================================================
#define GP 72
#define ST_AH 0
#define ST_BH 18432
#define ST_BYTES 36864
#define HG_SMEM (3*ST_BYTES)

__device__ __forceinline__ void hg_load_stage(uint32_t sb, int st, const __half* gB,
                                              int m0, int n0, int kc, int tid) {
    uint32_t base = sb + st * ST_BYTES;
    #pragma unroll
    for (int i = 0; i < 2; i++) {
        int idx = tid + i * 512;
        int row = idx >> 3, c8 = idx & 7;
        uint32_t so = (uint32_t)(row * GP + c8 * 8) * 2;
        cpa16(base + ST_AH + so, g_Ah + (size_t)(m0 + row) * Dq + kc + c8 * 8);
        cpa16(base + ST_BH + so, gB   + (size_t)(n0 + row) * Dq + kc + c8 * 8);
    }
}

__global__ void __launch_bounds__(512) k_hgemm(float* __restrict__ C, int sel) {
    extern __shared__ char smem[];
    uint32_t sb = smem_u32(smem);
    const __half* gB = sel ? g_Bh2 : g_Bh;
    int tid = threadIdx.x;
    int lane = tid & 31, w = tid >> 5;
    int wm = w & 3, wn = w >> 2;
    int m0 = blockIdx.y * 128;
    int n0 = blockIdx.x * 128;

    float acc[2][4][4];
    #pragma unroll
    for (int i = 0; i < 2; i++)
        #pragma unroll
        for (int j = 0; j < 4; j++)
            #pragma unroll
            for (int k = 0; k < 4; k++) acc[i][j][k] = 0.f;

    hg_load_stage(sb, 0, gB, m0, n0, 0, tid);
    cpa_commit();
    hg_load_stage(sb, 1, gB, m0, n0, 64, tid);
    cpa_commit();

    int aRow = lane & 15, aKo = (lane >> 4) << 3;
    int bRow = (lane & 7) + ((lane >> 4) << 3);
    int bKo = ((lane >> 3) & 1) << 3;

    for (int c = 0; c < 16; c++) {
        cpa_wait1();                       // group c complete
        __syncthreads();                   // data visible; all warps past compute c-1
        if (c + 2 < 16)
            hg_load_stage(sb, (c + 2) % 3, gB, m0, n0, (c + 2) * 64, tid);
        cpa_commit();                      // group c+2 (possibly empty)
        uint32_t s0 = sb + (c % 3) * ST_BYTES;
        #pragma unroll
        for (int kh = 0; kh < 4; kh++) {
            uint32_t ah[2][4], bh[4][2];
            #pragma unroll
            for (int mt = 0; mt < 2; mt++) {
                uint32_t off = (uint32_t)((wm * 32 + mt * 16 + aRow) * GP + kh * 16 + aKo) * 2;
                ldsm4(ah[mt], s0 + ST_AH + off);
            }
            #pragma unroll
            for (int nt2 = 0; nt2 < 2; nt2++) {
                uint32_t off = (uint32_t)((wn * 32 + nt2 * 16 + bRow) * GP + kh * 16 + bKo) * 2;
                uint32_t r[4];
                ldsm4(r, s0 + ST_BH + off);
                bh[nt2*2][0] = r[0]; bh[nt2*2][1] = r[1];
                bh[nt2*2+1][0] = r[2]; bh[nt2*2+1][1] = r[3];
            }
            #pragma unroll
            for (int mt = 0; mt < 2; mt++)
                #pragma unroll
                for (int nt = 0; nt < 4; nt++) mma16816(acc[mt][nt], ah[mt], bh[nt]);
        }
    }

    if (sel == 0) {
        #pragma unroll
        for (int mt = 0; mt < 2; mt++) {
            int r0 = m0 + wm * 32 + mt * 16 + (lane >> 2);
            #pragma unroll
            for (int nt = 0; nt < 4; nt++) {
                int col = n0 + wn * 32 + nt * 8 + (lane & 3) * 2;
                *(__half2*)(g_Vh + (size_t)r0 * Dq + col) =
                    __floats2half2_rn(acc[mt][nt][0], acc[mt][nt][1]);
                *(__half2*)(g_Vh + (size_t)(r0 + 8) * Dq + col) =
                    __floats2half2_rn(acc[mt][nt][2], acc[mt][nt][3]);
            }
        }
    } else {
        #pragma unroll
        for (int mt = 0; mt < 2; mt++) {
            int r0 = m0 + wm * 32 + mt * 16 + (lane >> 2);
            #pragma unroll
            for (int nt = 0; nt < 4; nt++) {
                int col = n0 + wn * 32 + nt * 8 + (lane & 3) * 2;
                *(float2*)(C + (size_t)r0 * Dq + col)       = make_float2(acc[mt][nt][0], acc[mt][nt][1]);
                *(float2*)(C + (size_t)(r0 + 8) * Dq + col) = make_float2(acc[mt][nt][2], acc[mt][nt][3]);
            }
        }
    }
}

// ===========================================================================
// fp32 -> fp16 convert into g_Ah
// ===========================================================================
__global__ void k_half(const float* __restrict__ x) {
    size_t i = ((size_t)blockIdx.x * 256 + threadIdx.x) * 4;
    float4 v = *(const float4*)(x + i);
    *(__half2*)(g_Ah + i)     = __floats2half2_rn(v.x, v.y);
    *(__half2*)(g_Ah + i + 2) = __floats2half2_rn(v.z, v.w);
}

// ===========================================================================
// fp32 W[k][n] -> transposed fp16 Wt[n][k]
// ===========================================================================
__global__ void k_halfT(const float* __restrict__ W, int sel) {
    __shared__ float t[32][33];
    __half* dst = sel ? g_Bh2 : g_Bh;
    int tx = threadIdx.x, ty = threadIdx.y;
    int bx = blockIdx.x, by = blockIdx.y;
    #pragma unroll
    for (int i = 0; i < 4; i++)
        t[ty + i*8][tx] = W[(size_t)(by*32 + ty + i*8) * Dq + bx*32 + tx];
    __syncthreads();
    #pragma unroll
    for (int i = 0; i < 4; i++) {
        size_t o = (size_t)(bx*32 + ty + i*8) * Dq + by*32 + tx;
        dst[o] = __float2half(t[tx][ty + i*8]);
    }
}

// ===========================================================================
// prepW: fold A into the second projections.
// W2Aq[k][h*64+d] = sum_f Wq2[k][h*64+f] * A[d,f]
// W2Ak[k][h*64+d] = sum_f Wk2[k][h*64+f] * A[f,d]     (Amat[f*64+d] = A[f,d])
// ===========================================================================
__global__ void k_prepW(const float* __restrict__ Wq2, const float* __restrict__ Wk2,
                        const float* __restrict__ Amat) {
    __shared__ float As[64][65];    // As[f][d] = A[f,d]
    __shared__ float Wq[32][68];
    __shared__ float Wk[32][68];
    int h = blockIdx.x, t = threadIdx.x;
    for (int i = t; i < 4096; i += 256) {
        int f = i >> 6, d = i & 63;
        As[f][d] = Amat[i];
    }
    for (int i = t; i < 2048; i += 256) {
        int k = i >> 6, f = i & 63;
        Wq[k][f] = Wq2[(size_t)k * 1024 + h*64 + f];
        Wk[k][f] = Wk2[(size_t)k * 1024 + h*64 + f];
    }
    __syncthreads();
    int k = t >> 3, d0 = (t & 7) * 8;
    #pragma unroll
    for (int j = 0; j < 8; j++) {
        int d = d0 + j;
        float sq = 0.f, sk = 0.f;
        #pragma unroll
        for (int f = 0; f < 64; f++) {
            sq += Wq[k][f] * As[d][f];   // A[d,f]
            sk += Wk[k][f] * As[f][d];   // A[f,d]
        }
        g_W2Aq[(size_t)k * 1024 + h*64 + d] = sq;
        g_W2Ak[(size_t)k * 1024 + h*64 + d] = sk;
    }
}

// ---------------------------------------------------------------------------
// proj1 v3: T = X @ W1.  64 rows x 32 cols/block, 3-stage cp.async, 8 acc.
// ---------------------------------------------------------------------------
#define P1_XS 0
#define P1_WS 17408                    // 64*68*4
#define P1_STAGE 26624                 // + 64*36*4 = 9216
#define P1_SMEM (3*P1_STAGE)           // 79872

__device__ __forceinline__ void p1_load(uint32_t sb, int st, const float* X,
                                        const float* W, int row0, int kc, int t) {
    uint32_t base = sb + st * P1_STAGE;
    #pragma unroll
    for (int i = 0; i < 4; i++) {
        int idx = t + i * 256;
        int r = idx >> 4, c4 = idx & 15;
        cpa16(base + P1_XS + (uint32_t)(r * 68 + c4 * 4) * 4,
              X + (size_t)(row0 + r) * 1024 + kc + c4 * 4);
    }
    #pragma unroll
    for (int i = 0; i < 2; i++) {
        int idx = t + i * 256;
        int k = idx >> 3, c4 = idx & 7;
        cpa16(base + P1_WS + (uint32_t)(k * 36 + c4 * 4) * 4,
              W + (size_t)(kc + k) * 32 + c4 * 4);
    }
}

__global__ void __launch_bounds__(256) k_proj1(const float* __restrict__ X,
                                               const float* __restrict__ W, int sel) {
    extern __shared__ char smem[];
    uint32_t sb = smem_u32(smem);
    float* T = sel ? g_Tk : g_Tq;
    int t = threadIdx.x;
    int row0 = blockIdx.x * 64;
    int tr = t >> 5, tc = t & 31;
    float acc[8] = {0.f,0.f,0.f,0.f,0.f,0.f,0.f,0.f};

    p1_load(sb, 0, X, W, row0, 0, t);
    cpa_commit();
    p1_load(sb, 1, X, W, row0, 64, t);
    cpa_commit();

    for (int c = 0; c < 16; c++) {
        cpa_wait1();
        __syncthreads();
        if (c + 2 < 16) p1_load(sb, (c + 2) % 3, X, W, row0, (c + 2) * 64, t);
        cpa_commit();
        const float* Xs = (const float*)(smem + (c % 3) * P1_STAGE);
        const float* Ws = (const float*)(smem + (c % 3) * P1_STAGE + P1_WS);
        #pragma unroll
        for (int k = 0; k < 64; k += 4) {
            float w0 = Ws[k*36 + tc], w1 = Ws[(k+1)*36 + tc];
            float w2 = Ws[(k+2)*36 + tc], w3 = Ws[(k+3)*36 + tc];
            #pragma unroll
            for (int i = 0; i < 8; i++) {
                float4 x = *(const float4*)&Xs[(tr*8 + i) * 68 + k];
                acc[i] += x.x*w0 + x.y*w1 + x.z*w2 + x.w*w3;
            }
        }
    }
    #pragma unroll
    for (int i = 0; i < 8; i++)
        T[(size_t)(row0 + tr*8 + i) * 32 + tc] = acc[i];
}

// ---------------------------------------------------------------------------
// s1exp: scores1 = Tk @ W2Ak (per head), exp (no max sub, |S|<~1), write
// E to attn in [bh,d,s] layout + row sums to g_L. grid (32 sblk, 128 bh).
// ---------------------------------------------------------------------------
__global__ void k_s1exp(float* __restrict__ attn) {
    __shared__ float Ts[64][33];
    __shared__ float Ws[32][68];
    __shared__ float wsum[8][16];
    int bh = blockIdx.y;
    int b = bh >> 4, h = bh & 15;
    int s0 = blockIdx.x * 64;
    int t = threadIdx.x;
    for (int i = t; i < 2048; i += 256) {
        int r = i >> 5, k = i & 31;
        Ts[r][k] = g_Tk[(size_t)(b * Sq + s0 + r) * 32 + k];
    }
    for (int i = t; i < 2048; i += 256) {
        int k = i >> 6, d = i & 63;
        Ws[k][d] = g_W2Ak[(size_t)k * 1024 + h*64 + d];
    }
    __syncthreads();
    int sl = t & 63, dg = t >> 6;
    float acc[16];
    #pragma unroll
    for (int i = 0; i < 16; i++) acc[i] = 0.f;
    #pragma unroll
    for (int k = 0; k < 32; k++) {
        float tk = Ts[sl][k];
        #pragma unroll
        for (int d4 = 0; d4 < 4; d4++) {
            float4 wv = *(const float4*)&Ws[k][dg*16 + d4*4];
            acc[d4*4]   += tk * wv.x;
            acc[d4*4+1] += tk * wv.y;
            acc[d4*4+2] += tk * wv.z;
            acc[d4*4+3] += tk * wv.w;
        }
    }
    float es[16];
    #pragma unroll
    for (int dd = 0; dd < 16; dd++) {
        float e = __expf(acc[dd] * 0.125f);
        es[dd] = e;
        attn[((size_t)(bh * 64 + dg*16 + dd)) * Sq + s0 + sl] = e;
    }
    #pragma unroll
    for (int dd = 0; dd < 16; dd++) {
        float v = es[dd];
        #pragma unroll
        for (int o = 16; o > 0; o >>= 1) v += __shfl_xor_sync(0xffffffffu, v, o);
        if ((t & 31) == 0) wsum[t >> 5][dd] = v;
    }
    __syncthreads();
    if (t < 64) {
        int dgg = t >> 4, dd = t & 15;
        atomicAdd(&g_L[bh*64 + dgg*16 + dd], wsum[dgg*2][dd] + wsum[dgg*2 + 1][dd]);
    }
}

// ---------------------------------------------------------------------------
// vv: normalize attn in place and accumulate VV (V fp16).
// ---------------------------------------------------------------------------
__global__ void k_vv(float* __restrict__ attn) {
    __shared__ float At[64][65];
    __shared__ float Vs[64][65];
    __shared__ float inv[64];
    int split = blockIdx.x;
    int bh = blockIdx.y;
    int b = bh >> 4, h = bh & 15;
    int t = threadIdx.x;
    int tr = t >> 4, tc = t & 15;
    if (t < 64) inv[t] = 1.f / g_L[bh*64 + t];
    __syncthreads();
    float acc[4][4];
    #pragma unroll
    for (int i = 0; i < 4; i++)
        #pragma unroll
        for (int j = 0; j < 4; j++) acc[i][j] = 0.f;
    int sbeg = split * 512;
    for (int sc0 = sbeg; sc0 < sbeg + 512; sc0 += 64) {
        for (int i = t; i < 4096; i += 256) {
            int d = i >> 6, ss = i & 63;
            size_t idx = ((size_t)(bh * 64 + d)) * Sq + sc0 + ss;
            float en = attn[idx] * inv[d];
            At[d][ss] = en;
            attn[idx] = en;
        }
        for (int i = t; i < 4096; i += 256) {
            int ss = i >> 6, f = i & 63;
            Vs[ss][f] = __half2float(g_Vh[(size_t)(b * Sq + sc0 + ss) * 1024 + h * 64 + f]);
        }
        __syncthreads();
        #pragma unroll 8
        for (int ss = 0; ss < 64; ss++) {
            float av[4], bv[4];
            #pragma unroll
            for (int i = 0; i < 4; i++) av[i] = At[tr * 4 + i][ss];
            #pragma unroll
            for (int j = 0; j < 4; j++) bv[j] = Vs[ss][tc * 4 + j];
            #pragma unroll
            for (int i = 0; i < 4; i++)
                #pragma unroll
                for (int j = 0; j < 4; j++) acc[i][j] += av[i] * bv[j];
        }
        __syncthreads();
    }
    #pragma unroll
    for (int i = 0; i < 4; i++)
        #pragma unroll
        for (int j = 0; j < 4; j++)
            atomicAdd(&g_VV[(size_t)bh * 4096 + (tr * 4 + i) * 64 + tc * 4 + j], acc[i][j]);
}

// ---------------------------------------------------------------------------
// stage 2: scores2 = Tq @ W2Aq (fp32 in-kernel), fp32 softmax, P@VV via mma.
// Block 128 threads, 128 s rows. grid (16, 128).
// ---------------------------------------------------------------------------
#define S2_TS   0                       // float Ts[128][33]   16896
#define S2_WS   16896                   // float Ws[32][68]     8704
#define S2_LINV 25600                   // float Linv[128]       512
#define S2_PH   26112                   // half  Ph[128][72]   18432
#define S2_VT   44544                   // half  Vt[64][72]     9216
#define S2_SMEM 53760

__global__ void __launch_bounds__(128) k_stage2() {
    extern __shared__ char smem[];
    uint32_t sb = smem_u32(smem);
    float* Ts   = (float*)(smem + S2_TS);
    float* Ws   = (float*)(smem + S2_WS);
    float* Linv = (float*)(smem + S2_LINV);
    __half* Ph  = (__half*)(smem + S2_PH);
    __half* Vt  = (__half*)(smem + S2_VT);
    int bh = blockIdx.y;
    int b = bh >> 4, h = bh & 15;
    int s0 = blockIdx.x * 128;
    int t = threadIdx.x, lane = t & 31, w = t >> 5;

    for (int i = t; i < 4096; i += 128) {          // Tq tile 128x32
        int r = i >> 5, k = i & 31;
        Ts[r*33 + k] = g_Tq[(size_t)(b * Sq + s0 + r) * 32 + k];
    }
    for (int i = t; i < 2048; i += 128) {          // W2Aq slice [k][d]
        int k = i >> 6, d = i & 63;
        Ws[k*68 + d] = g_W2Aq[(size_t)k * 1024 + h*64 + d];
    }
    for (int i = t; i < 4096; i += 128) {          // VV^T fp16 [f][d]
        int d = i >> 6, f = i & 63;
        Vt[f*72 + d] = __float2half(g_VV[(size_t)bh * 4096 + i]);
    }
    __syncthreads();

    // scores2 row t (fp32), then softmax, then P fp16
    {
        float sc[64];
        #pragma unroll
        for (int d = 0; d < 64; d++) sc[d] = 0.f;
        #pragma unroll
        for (int k = 0; k < 32; k++) {
            float tq = Ts[t*33 + k];
            #pragma unroll
            for (int d4 = 0; d4 < 16; d4++) {
                float4 wv = *(const float4*)&Ws[k*68 + d4*4];
                sc[d4*4]   += tq * wv.x;
                sc[d4*4+1] += tq * wv.y;
                sc[d4*4+2] += tq * wv.z;
                sc[d4*4+3] += tq * wv.w;
            }
        }
        float m = -1e30f;
        #pragma unroll
        for (int d = 0; d < 64; d++) { sc[d] *= 0.125f; m = fmaxf(m, sc[d]); }
        float l = 0.f;
        #pragma unroll
        for (int d = 0; d < 64; d++) { float e = __expf(sc[d] - m); sc[d] = e; l += e; }
        Linv[t] = 1.f / l;
        #pragma unroll
        for (int d = 0; d < 64; d++) Ph[t*72 + d] = __float2half(sc[d]);
    }
    __syncthreads();

    // out = P @ VV via mma
    int aRow = lane & 15, aKo = (lane >> 4) << 3;
    int bRow = (lane & 7) + ((lane >> 4) << 3);
    int bKo = ((lane >> 3) & 1) << 3;
    {
        float acc[2][8][4];
        #pragma unroll
        for (int i = 0; i < 2; i++)
            #pragma unroll
            for (int j = 0; j < 8; j++)
                #pragma unroll
                for (int k = 0; k < 4; k++) acc[i][j][k] = 0.f;
        #pragma unroll
        for (int ks = 0; ks < 4; ks++) {
            uint32_t aq[2][4], bf[8][2];
            #pragma unroll
            for (int mt = 0; mt < 2; mt++)
                ldsm4(aq[mt], sb + S2_PH +
                      (uint32_t)((w*32 + mt*16 + aRow) * 72 + ks*16 + aKo) * 2);
            #pragma unroll
            for (int g = 0; g < 4; g++) {
                uint32_t r[4];
                ldsm4(r, sb + S2_VT + (uint32_t)((g*16 + bRow) * 72 + ks*16 + bKo) * 2);
                bf[g*2][0] = r[0]; bf[g*2][1] = r[1];
                bf[g*2+1][0] = r[2]; bf[g*2+1][1] = r[3];
            }
            #pragma unroll
            for (int mt = 0; mt < 2; mt++)
                #pragma unroll
                for (int nt = 0; nt < 8; nt++) mma16816(acc[mt][nt], aq[mt], bf[nt]);
        }
        #pragma unroll
        for (int mt = 0; mt < 2; mt++) {
            int r0 = w*32 + mt*16 + (lane >> 2);
            float inv0 = Linv[r0], inv1 = Linv[r0 + 8];
            float* O0 = g_VVV + ((size_t)bh * Sq + s0 + r0) * 64;
            float* O1 = g_VVV + ((size_t)bh * Sq + s0 + r0 + 8) * 64;
            #pragma unroll
            for (int nt = 0; nt < 8; nt++) {
                int c = nt*8 + (lane & 3) * 2;
                *(float2*)(O0 + c) = make_float2(acc[mt][nt][0] * inv0, acc[mt][nt][1] * inv0);
                *(float2*)(O1 + c) = make_float2(acc[mt][nt][2] * inv1, acc[mt][nt][3] * inv1);
            }
        }
    }
}

// ---------------------------------------------------------------------------
// LayerNorm (1024), x = in1 + res.
// sel=0: in1=g_VVV, res=Xq, out=g_O1 + fp16 g_Ah.  sel=1: in1=g_O2, res=g_O1, out=d_out.
// ---------------------------------------------------------------------------
__global__ void k_ln(const float* __restrict__ rese, const float* __restrict__ g,
                     const float* __restrict__ bb, float* __restrict__ oute, int sel) {
    const float* in1 = sel ? g_O2 : g_VVV;
    const float* res = sel ? g_O1 : rese;
    float* out = sel ? oute : g_O1;
    __shared__ float sm1[8];
    __shared__ float sm2[8];
    size_t base = (size_t)blockIdx.x * 1024;
    int t = threadIdx.x;
    float v[4];
    float sum = 0.f;
    #pragma unroll
    for (int i = 0; i < 4; i++) {
        int c = t + i * 256;
        v[i] = in1[base + c] + res[base + c];
        sum += v[i];
    }
    #pragma unroll
    for (int o = 16; o > 0; o >>= 1) sum += __shfl_xor_sync(0xffffffffu, sum, o);
    if ((t & 31) == 0) sm1[t >> 5] = sum;
    __syncthreads();
    sum = 0.f;
    #pragma unroll
    for (int i = 0; i < 8; i++) sum += sm1[i];
    float mean = sum * (1.f / 1024.f);
    float sq = 0.f;
    #pragma unroll
    for (int i = 0; i < 4; i++) { float d = v[i] - mean; sq += d * d; }
    #pragma unroll
    for (int o = 16; o > 0; o >>= 1) sq += __shfl_xor_sync(0xffffffffu, sq, o);
    if ((t & 31) == 0) sm2[t >> 5] = sq;
    __syncthreads();
    sq = 0.f;
    #pragma unroll
    for (int i = 0; i < 8; i++) sq += sm2[i];
    float rstd = rsqrtf(sq * (1.f / 1024.f) + 1e-5f);
    #pragma unroll
    for (int i = 0; i < 4; i++) {
        int c = t + i * 256;
        float o = (v[i] - mean) * rstd * g[c] + bb[c];
        out[base + c] = o;
        if (sel == 0) g_Ah[base + c] = __float2half(o);
    }
}

// ===========================================================================
// Host side — single stream.
// ===========================================================================
extern "C" void kernel_launch(void* const* d_in, const int* in_sizes, int n_in,
                              void* d_out, int out_size) {
    const float* Xq  = (const float*)d_in[0];
    const float* Xk  = (const float*)d_in[1];
    const float* Xv  = (const float*)d_in[2];
    const float* Wq1 = (const float*)d_in[3];
    const float* Wq2 = (const float*)d_in[4];
    const float* Wk1 = (const float*)d_in[5];
    const float* Wk2 = (const float*)d_in[6];
    const float* Wv  = (const float*)d_in[7];
    const float* Wfc = (const float*)d_in[8];
    const float* Am  = (const float*)d_in[9];
    const float* lng = (const float*)d_in[10];
    const float* lnb = (const float*)d_in[11];
    float* out = (float*)d_out;
    size_t attn_off = (out_size > OUT_MAIN) ? (size_t)(out_size - OUT_MAIN) : 0;
    float* attn = out + attn_off;

    void *pO2, *pVV, *pL;
    cudaGetSymbolAddress(&pO2, g_O2);
    cudaGetSymbolAddress(&pVV, g_VV);
    cudaGetSymbolAddress(&pL,  g_L);

    cudaFuncSetAttribute(k_hgemm,  cudaFuncAttributeMaxDynamicSharedMemorySize, HG_SMEM);
    cudaFuncSetAttribute(k_proj1,  cudaFuncAttributeMaxDynamicSharedMemorySize, P1_SMEM);
    cudaFuncSetAttribute(k_stage2, cudaFuncAttributeMaxDynamicSharedMemorySize, S2_SMEM);

    k_half<<<16384, 256>>>(Xv);
    k_halfT<<<dim3(32, 32), dim3(32, 8)>>>(Wv, 0);
    k_prepW<<<16, 256>>>(Wq2, Wk2, Am);
    k_proj1<<<256, 256, P1_SMEM>>>(Xq, Wq1, 0);
    k_proj1<<<256, 256, P1_SMEM>>>(Xk, Wk1, 1);

    k_hgemm<<<dim3(8, 128), 512, HG_SMEM>>>(nullptr, 0);    // V -> g_Vh

    cudaMemsetAsync(pL,  0, (size_t)BHn * DHq * sizeof(float));
    cudaMemsetAsync(pVV, 0, (size_t)BHn * DHq * DHq * sizeof(float));
    k_s1exp<<<dim3(32, 128), 256>>>(attn);                  // E + row sums
    k_vv<<<dim3(4, 128), 256>>>(attn);                      // normalize + VV
    k_stage2<<<dim3(16, 128), 128, S2_SMEM>>>();            // scores2+softmax+P@VV
    k_ln<<<16384, 256>>>(Xq, lng, lnb, nullptr, 0);         // out1 + fp16

    k_halfT<<<dim3(32, 32), dim3(32, 8)>>>(Wfc, 1);
    k_hgemm<<<dim3(8, 128), 512, HG_SMEM>>>((float*)pO2, 1);
    k_ln<<<16384, 256>>>(nullptr, lng, lnb, out, 1);        // out
}

// round 13
// speedup vs baseline: 1.4248x; 1.0188x over previous
#include <cuda_runtime.h>
#include <cuda_fp16.h>
#include <cstdint>

// Problem constants
#define Bq   8
#define Sq   2048
#define Dq   1024
#define Hq   16
#define DHq  64
#define Mrows (Bq*Sq)        // 16384
#define BHn   (Bq*Hq)        // 128
#define OUT_MAIN (Mrows*Dq)  // 16777216 floats of `outputs`

__device__ float g_Tq[Mrows*32];
__device__ float g_Tk[Mrows*32];
__device__ float g_VV[BHn*DHq*DHq];
__device__ float g_VVV[Mrows*Dq];
__device__ float g_O1[Mrows*Dq];
__device__ float g_O2[Mrows*Dq];
__device__ float g_L [BHn*DHq];
__device__ float g_W2Aq[32*Dq];
__device__ float g_W2Ak[32*Dq];

// fp16 buffers
__device__ __align__(128) __half g_Ah [Mrows*Dq];
__device__ __align__(128) __half g_Vh [Mrows*Dq];
__device__ __align__(128) __half g_Bh [Dq*Dq];
__device__ __align__(128) __half g_Bh2[Dq*Dq];

// ===========================================================================
// PTX helpers
// ===========================================================================
__device__ __forceinline__ uint32_t smem_u32(const void* p) {
    uint32_t a;
    asm("{ .reg .u64 t; cvta.to.shared.u64 t, %1; cvt.u32.u64 %0, t; }" : "=r"(a) : "l"(p));
    return a;
}
__device__ __forceinline__ void cpa16(uint32_t s, const void* g) {
    asm volatile("cp.async.cg.shared.global [%0], [%1], 16;" :: "r"(s), "l"(g));
}
__device__ __forceinline__ void cpa_commit() {
    asm volatile("cp.async.commit_group;" ::: "memory");
}
__device__ __forceinline__ void cpa_wait1() {
    asm volatile("cp.async.wait_group 1;" ::: "memory");
}
__device__ __forceinline__ void ldsm4(uint32_t* r, uint32_t addr) {
    asm volatile("ldmatrix.sync.aligned.m8n8.x4.shared.b16 {%0,%1,%2,%3}, [%4];"
                 : "=r"(r[0]), "=r"(r[1]), "=r"(r[2]), "=r"(r[3]) : "r"(addr));
}
__device__ __forceinline__ void mma16816(float* c, const uint32_t* a, const uint32_t* b) {
    asm volatile(
        "mma.sync.aligned.m16n8k16.row.col.f32.f16.f16.f32 "
        "{%0,%1,%2,%3}, {%4,%5,%6,%7}, {%8,%9}, {%0,%1,%2,%3};"
        : "+f"(c[0]), "+f"(c[1]), "+f"(c[2]), "+f"(c[3])
        : "r"(a[0]), "r"(a[1]), "r"(a[2]), "r"(a[3]), "r"(b[0]), "r"(b[1]));
}

// ===========================================================================
// HMMA GEMM: 512 threads, 16 warps of 32x32, K-chunk 64, 3-stage / 1 sync.
// (3-stage ring: prefetch target (c+2)%3 never equals compute stage c%3.)
// ===========================================================================
#define GP 72
#define ST_AH 0
#define ST_BH 18432
#define ST_BYTES 36864
#define HG_SMEM (3*ST_BYTES)

__device__ __forceinline__ void hg_load_stage(uint32_t sb, int st, const __half* gB,
                                              int m0, int n0, int kc, int tid) {
    uint32_t base = sb + st * ST_BYTES;
    #pragma unroll
    for (int i = 0; i < 2; i++) {
        int idx = tid + i * 512;
        int row = idx >> 3, c8 = idx & 7;
        uint32_t so = (uint32_t)(row * GP + c8 * 8) * 2;
        cpa16(base + ST_AH + so, g_Ah + (size_t)(m0 + row) * Dq + kc + c8 * 8);
        cpa16(base + ST_BH + so, gB   + (size_t)(n0 + row) * Dq + kc + c8 * 8);
    }
}

__global__ void __launch_bounds__(512) k_hgemm(float* __restrict__ C, int sel) {
    extern __shared__ char smem[];
    uint32_t sb = smem_u32(smem);
    const __half* gB = sel ? g_Bh2 : g_Bh;
    int tid = threadIdx.x;
    int lane = tid & 31, w = tid >> 5;
    int wm = w & 3, wn = w >> 2;
    int m0 = blockIdx.y * 128;
    int n0 = blockIdx.x * 128;

    float acc[2][4][4];
    #pragma unroll
    for (int i = 0; i < 2; i++)
        #pragma unroll
        for (int j = 0; j < 4; j++)
            #pragma unroll
            for (int k = 0; k < 4; k++) acc[i][j][k] = 0.f;

    hg_load_stage(sb, 0, gB, m0, n0, 0, tid);
    cpa_commit();
    hg_load_stage(sb, 1, gB, m0, n0, 64, tid);
    cpa_commit();

    int aRow = lane & 15, aKo = (lane >> 4) << 3;
    int bRow = (lane & 7) + ((lane >> 4) << 3);
    int bKo = ((lane >> 3) & 1) << 3;

    for (int c = 0; c < 16; c++) {
        cpa_wait1();
        __syncthreads();
        if (c + 2 < 16)
            hg_load_stage(sb, (c + 2) % 3, gB, m0, n0, (c + 2) * 64, tid);
        cpa_commit();
        uint32_t s0 = sb + (c % 3) * ST_BYTES;
        #pragma unroll
        for (int kh = 0; kh < 4; kh++) {
            uint32_t ah[2][4], bh[4][2];
            #pragma unroll
            for (int mt = 0; mt < 2; mt++) {
                uint32_t off = (uint32_t)((wm * 32 + mt * 16 + aRow) * GP + kh * 16 + aKo) * 2;
                ldsm4(ah[mt], s0 + ST_AH + off);
            }
            #pragma unroll
            for (int nt2 = 0; nt2 < 2; nt2++) {
                uint32_t off = (uint32_t)((wn * 32 + nt2 * 16 + bRow) * GP + kh * 16 + bKo) * 2;
                uint32_t r[4];
                ldsm4(r, s0 + ST_BH + off);
                bh[nt2*2][0] = r[0]; bh[nt2*2][1] = r[1];
                bh[nt2*2+1][0] = r[2]; bh[nt2*2+1][1] = r[3];
            }
            #pragma unroll
            for (int mt = 0; mt < 2; mt++)
                #pragma unroll
                for (int nt = 0; nt < 4; nt++) mma16816(acc[mt][nt], ah[mt], bh[nt]);
        }
    }

    if (sel == 0) {
        #pragma unroll
        for (int mt = 0; mt < 2; mt++) {
            int r0 = m0 + wm * 32 + mt * 16 + (lane >> 2);
            #pragma unroll
            for (int nt = 0; nt < 4; nt++) {
                int col = n0 + wn * 32 + nt * 8 + (lane & 3) * 2;
                *(__half2*)(g_Vh + (size_t)r0 * Dq + col) =
                    __floats2half2_rn(acc[mt][nt][0], acc[mt][nt][1]);
                *(__half2*)(g_Vh + (size_t)(r0 + 8) * Dq + col) =
                    __floats2half2_rn(acc[mt][nt][2], acc[mt][nt][3]);
            }
        }
    } else {
        #pragma unroll
        for (int mt = 0; mt < 2; mt++) {
            int r0 = m0 + wm * 32 + mt * 16 + (lane >> 2);
            #pragma unroll
            for (int nt = 0; nt < 4; nt++) {
                int col = n0 + wn * 32 + nt * 8 + (lane & 3) * 2;
                *(float2*)(C + (size_t)r0 * Dq + col)       = make_float2(acc[mt][nt][0], acc[mt][nt][1]);
                *(float2*)(C + (size_t)(r0 + 8) * Dq + col) = make_float2(acc[mt][nt][2], acc[mt][nt][3]);
            }
        }
    }
}

// ===========================================================================
// fp32 -> fp16 convert into g_Ah
// ===========================================================================
__global__ void k_half(const float* __restrict__ x) {
    size_t i = ((size_t)blockIdx.x * 256 + threadIdx.x) * 4;
    float4 v = *(const float4*)(x + i);
    *(__half2*)(g_Ah + i)     = __floats2half2_rn(v.x, v.y);
    *(__half2*)(g_Ah + i + 2) = __floats2half2_rn(v.z, v.w);
}

// ===========================================================================
// fp32 W[k][n] -> transposed fp16 Wt[n][k]
// ===========================================================================
__global__ void k_halfT(const float* __restrict__ W, int sel) {
    __shared__ float t[32][33];
    __half* dst = sel ? g_Bh2 : g_Bh;
    int tx = threadIdx.x, ty = threadIdx.y;
    int bx = blockIdx.x, by = blockIdx.y;
    #pragma unroll
    for (int i = 0; i < 4; i++)
        t[ty + i*8][tx] = W[(size_t)(by*32 + ty + i*8) * Dq + bx*32 + tx];
    __syncthreads();
    #pragma unroll
    for (int i = 0; i < 4; i++) {
        size_t o = (size_t)(bx*32 + ty + i*8) * Dq + by*32 + tx;
        dst[o] = __float2half(t[tx][ty + i*8]);
    }
}

// ===========================================================================
// prepW: fold A into the second projections.
// ===========================================================================
__global__ void k_prepW(const float* __restrict__ Wq2, const float* __restrict__ Wk2,
                        const float* __restrict__ Amat) {
    __shared__ float As[64][65];
    __shared__ float Wq[32][68];
    __shared__ float Wk[32][68];
    int h = blockIdx.x, t = threadIdx.x;
    for (int i = t; i < 4096; i += 256) {
        int f = i >> 6, d = i & 63;
        As[f][d] = Amat[i];
    }
    for (int i = t; i < 2048; i += 256) {
        int k = i >> 6, f = i & 63;
        Wq[k][f] = Wq2[(size_t)k * 1024 + h*64 + f];
        Wk[k][f] = Wk2[(size_t)k * 1024 + h*64 + f];
    }
    __syncthreads();
    int k = t >> 3, d0 = (t & 7) * 8;
    #pragma unroll
    for (int j = 0; j < 8; j++) {
        int d = d0 + j;
        float sq = 0.f, sk = 0.f;
        #pragma unroll
        for (int f = 0; f < 64; f++) {
            sq += Wq[k][f] * As[d][f];
            sk += Wk[k][f] * As[f][d];
        }
        g_W2Aq[(size_t)k * 1024 + h*64 + d] = sq;
        g_W2Ak[(size_t)k * 1024 + h*64 + d] = sk;
    }
}

// ===========================================================================
// zero T buffers.  512 blocks x 256 threads x 4 floats = 524288 = Mrows*32.
// ===========================================================================
__global__ void k_zeroT() {
    size_t i = ((size_t)blockIdx.x * 256 + threadIdx.x) * 4;
    *(float4*)(g_Tq + i) = make_float4(0.f, 0.f, 0.f, 0.f);
    *(float4*)(g_Tk + i) = make_float4(0.f, 0.f, 0.f, 0.f);
}

// ---------------------------------------------------------------------------
// proj1 v4 FIXED: T += X @ W1 over a 256-wide K slice. grid (4 ksplit, 256).
// 2-stage double buffer, COMPUTE-THEN-LOAD order (prefetch for c+2 is issued
// only after all warps finished computing stage c&1 — no producer/consumer
// clash; overlap happens against compute of c+1 on the other stage).
// ---------------------------------------------------------------------------
#define P1_XS 0
#define P1_WS 17408                    // 64*68*4
#define P1_STAGE 26624                 // + 64*36*4
#define P1_SMEM (2*P1_STAGE)           // 53248

__device__ __forceinline__ void p1_load(uint32_t sb, int st, const float* X,
                                        const float* W, int row0, int kc, int t) {
    uint32_t base = sb + st * P1_STAGE;
    #pragma unroll
    for (int i = 0; i < 4; i++) {
        int idx = t + i * 256;
        int r = idx >> 4, c4 = idx & 15;
        cpa16(base + P1_XS + (uint32_t)(r * 68 + c4 * 4) * 4,
              X + (size_t)(row0 + r) * 1024 + kc + c4 * 4);
    }
    #pragma unroll
    for (int i = 0; i < 2; i++) {
        int idx = t + i * 256;
        int k = idx >> 3, c4 = idx & 7;
        cpa16(base + P1_WS + (uint32_t)(k * 36 + c4 * 4) * 4,
              W + (size_t)(kc + k) * 32 + c4 * 4);
    }
}

__global__ void __launch_bounds__(256) k_proj1(const float* __restrict__ X,
                                               const float* __restrict__ W, int sel) {
    extern __shared__ char smem[];
    uint32_t sb = smem_u32(smem);
    float* T = sel ? g_Tk : g_Tq;
    int t = threadIdx.x;
    int row0 = blockIdx.y * 64;
    int k0 = blockIdx.x * 256;
    int tr = t >> 5, tc = t & 31;
    float acc[8] = {0.f,0.f,0.f,0.f,0.f,0.f,0.f,0.f};

    p1_load(sb, 0, X, W, row0, k0, t);
    cpa_commit();
    p1_load(sb, 1, X, W, row0, k0 + 64, t);
    cpa_commit();
    cpa_wait1();                       // stage 0 ready
    __syncthreads();

    for (int c = 0; c < 4; c++) {
        const float* Xs = (const float*)(smem + (c & 1) * P1_STAGE);
        const float* Ws = (const float*)(smem + (c & 1) * P1_STAGE + P1_WS);
        #pragma unroll
        for (int k = 0; k < 64; k += 4) {
            float w0 = Ws[k*36 + tc], w1 = Ws[(k+1)*36 + tc];
            float w2 = Ws[(k+2)*36 + tc], w3 = Ws[(k+3)*36 + tc];
            #pragma unroll
            for (int i = 0; i < 8; i++) {
                float4 x = *(const float4*)&Xs[(tr*8 + i) * 68 + k];
                acc[i] += x.x*w0 + x.y*w1 + x.z*w2 + x.w*w3;
            }
        }
        __syncthreads();               // all warps done with stage c&1
        if (c + 2 < 4) p1_load(sb, c & 1, X, W, row0, k0 + (c + 2) * 64, t);
        cpa_commit();
        cpa_wait1();                   // next stage ready
        __syncthreads();
    }
    #pragma unroll
    for (int i = 0; i < 8; i++)
        atomicAdd(&T[(size_t)(row0 + tr*8 + i) * 32 + tc], acc[i]);
}

// ---------------------------------------------------------------------------
// s1exp: scores1 = Tk @ W2Ak, exp, write E [bh,d,s] + row sums.
// ---------------------------------------------------------------------------
__global__ void k_s1exp(float* __restrict__ attn) {
    __shared__ float Ts[64][33];
    __shared__ float Ws[32][68];
    __shared__ float wsum[8][16];
    int bh = blockIdx.y;
    int b = bh >> 4, h = bh & 15;
    int s0 = blockIdx.x * 64;
    int t = threadIdx.x;
    for (int i = t; i < 2048; i += 256) {
        int r = i >> 5, k = i & 31;
        Ts[r][k] = g_Tk[(size_t)(b * Sq + s0 + r) * 32 + k];
    }
    for (int i = t; i < 2048; i += 256) {
        int k = i >> 6, d = i & 63;
        Ws[k][d] = g_W2Ak[(size_t)k * 1024 + h*64 + d];
    }
    __syncthreads();
    int sl = t & 63, dg = t >> 6;
    float acc[16];
    #pragma unroll
    for (int i = 0; i < 16; i++) acc[i] = 0.f;
    #pragma unroll
    for (int k = 0; k < 32; k++) {
        float tk = Ts[sl][k];
        #pragma unroll
        for (int d4 = 0; d4 < 4; d4++) {
            float4 wv = *(const float4*)&Ws[k][dg*16 + d4*4];
            acc[d4*4]   += tk * wv.x;
            acc[d4*4+1] += tk * wv.y;
            acc[d4*4+2] += tk * wv.z;
            acc[d4*4+3] += tk * wv.w;
        }
    }
    float es[16];
    #pragma unroll
    for (int dd = 0; dd < 16; dd++) {
        float e = __expf(acc[dd] * 0.125f);
        es[dd] = e;
        attn[((size_t)(bh * 64 + dg*16 + dd)) * Sq + s0 + sl] = e;
    }
    #pragma unroll
    for (int dd = 0; dd < 16; dd++) {
        float v = es[dd];
        #pragma unroll
        for (int o = 16; o > 0; o >>= 1) v += __shfl_xor_sync(0xffffffffu, v, o);
        if ((t & 31) == 0) wsum[t >> 5][dd] = v;
    }
    __syncthreads();
    if (t < 64) {
        int dgg = t >> 4, dd = t & 15;
        atomicAdd(&g_L[bh*64 + dgg*16 + dd], wsum[dgg*2][dd] + wsum[dgg*2 + 1][dd]);
    }
}

// ---------------------------------------------------------------------------
// vv: normalize attn in place and accumulate VV (V fp16).
// ---------------------------------------------------------------------------
__global__ void k_vv(float* __restrict__ attn) {
    __shared__ float At[64][65];
    __shared__ float Vs[64][65];
    __shared__ float inv[64];
    int split = blockIdx.x;
    int bh = blockIdx.y;
    int b = bh >> 4, h = bh & 15;
    int t = threadIdx.x;
    int tr = t >> 4, tc = t & 15;
    if (t < 64) inv[t] = 1.f / g_L[bh*64 + t];
    __syncthreads();
    float acc[4][4];
    #pragma unroll
    for (int i = 0; i < 4; i++)
        #pragma unroll
        for (int j = 0; j < 4; j++) acc[i][j] = 0.f;
    int sbeg = split * 512;
    for (int sc0 = sbeg; sc0 < sbeg + 512; sc0 += 64) {
        for (int i = t; i < 4096; i += 256) {
            int d = i >> 6, ss = i & 63;
            size_t idx = ((size_t)(bh * 64 + d)) * Sq + sc0 + ss;
            float en = attn[idx] * inv[d];
            At[d][ss] = en;
            attn[idx] = en;
        }
        for (int i = t; i < 4096; i += 256) {
            int ss = i >> 6, f = i & 63;
            Vs[ss][f] = __half2float(g_Vh[(size_t)(b * Sq + sc0 + ss) * 1024 + h * 64 + f]);
        }
        __syncthreads();
        #pragma unroll 8
        for (int ss = 0; ss < 64; ss++) {
            float av[4], bv[4];
            #pragma unroll
            for (int i = 0; i < 4; i++) av[i] = At[tr * 4 + i][ss];
            #pragma unroll
            for (int j = 0; j < 4; j++) bv[j] = Vs[ss][tc * 4 + j];
            #pragma unroll
            for (int i = 0; i < 4; i++)
                #pragma unroll
                for (int j = 0; j < 4; j++) acc[i][j] += av[i] * bv[j];
        }
        __syncthreads();
    }
    #pragma unroll
    for (int i = 0; i < 4; i++)
        #pragma unroll
        for (int j = 0; j < 4; j++)
            atomicAdd(&g_VV[(size_t)bh * 4096 + (tr * 4 + i) * 64 + tc * 4 + j], acc[i][j]);
}

// ---------------------------------------------------------------------------
// stage 2: scores2 = Tq @ W2Aq (fp32), fp32 softmax, P@VV via mma.
// ---------------------------------------------------------------------------
#define S2_TS   0
#define S2_WS   16896
#define S2_LINV 25600
#define S2_PH   26112
#define S2_VT   44544
#define S2_SMEM 53760

__global__ void __launch_bounds__(128) k_stage2() {
    extern __shared__ char smem[];
    uint32_t sb = smem_u32(smem);
    float* Ts   = (float*)(smem + S2_TS);
    float* Ws   = (float*)(smem + S2_WS);
    float* Linv = (float*)(smem + S2_LINV);
    __half* Ph  = (__half*)(smem + S2_PH);
    __half* Vt  = (__half*)(smem + S2_VT);
    int bh = blockIdx.y;
    int b = bh >> 4, h = bh & 15;
    int s0 = blockIdx.x * 128;
    int t = threadIdx.x, lane = t & 31, w = t >> 5;

    for (int i = t; i < 4096; i += 128) {
        int r = i >> 5, k = i & 31;
        Ts[r*33 + k] = g_Tq[(size_t)(b * Sq + s0 + r) * 32 + k];
    }
    for (int i = t; i < 2048; i += 128) {
        int k = i >> 6, d = i & 63;
        Ws[k*68 + d] = g_W2Aq[(size_t)k * 1024 + h*64 + d];
    }
    for (int i = t; i < 4096; i += 128) {
        int d = i >> 6, f = i & 63;
        Vt[f*72 + d] = __float2half(g_VV[(size_t)bh * 4096 + i]);
    }
    __syncthreads();

    {
        float sc[64];
        #pragma unroll
        for (int d = 0; d < 64; d++) sc[d] = 0.f;
        #pragma unroll
        for (int k = 0; k < 32; k++) {
            float tq = Ts[t*33 + k];
            #pragma unroll
            for (int d4 = 0; d4 < 16; d4++) {
                float4 wv = *(const float4*)&Ws[k*68 + d4*4];
                sc[d4*4]   += tq * wv.x;
                sc[d4*4+1] += tq * wv.y;
                sc[d4*4+2] += tq * wv.z;
                sc[d4*4+3] += tq * wv.w;
            }
        }
        float m = -1e30f;
        #pragma unroll
        for (int d = 0; d < 64; d++) { sc[d] *= 0.125f; m = fmaxf(m, sc[d]); }
        float l = 0.f;
        #pragma unroll
        for (int d = 0; d < 64; d++) { float e = __expf(sc[d] - m); sc[d] = e; l += e; }
        Linv[t] = 1.f / l;
        #pragma unroll
        for (int d = 0; d < 64; d++) Ph[t*72 + d] = __float2half(sc[d]);
    }
    __syncthreads();

    int aRow = lane & 15, aKo = (lane >> 4) << 3;
    int bRow = (lane & 7) + ((lane >> 4) << 3);
    int bKo = ((lane >> 3) & 1) << 3;
    {
        float acc[2][8][4];
        #pragma unroll
        for (int i = 0; i < 2; i++)
            #pragma unroll
            for (int j = 0; j < 8; j++)
                #pragma unroll
                for (int k = 0; k < 4; k++) acc[i][j][k] = 0.f;
        #pragma unroll
        for (int ks = 0; ks < 4; ks++) {
            uint32_t aq[2][4], bf[8][2];
            #pragma unroll
            for (int mt = 0; mt < 2; mt++)
                ldsm4(aq[mt], sb + S2_PH +
                      (uint32_t)((w*32 + mt*16 + aRow) * 72 + ks*16 + aKo) * 2);
            #pragma unroll
            for (int g = 0; g < 4; g++) {
                uint32_t r[4];
                ldsm4(r, sb + S2_VT + (uint32_t)((g*16 + bRow) * 72 + ks*16 + bKo) * 2);
                bf[g*2][0] = r[0]; bf[g*2][1] = r[1];
                bf[g*2+1][0] = r[2]; bf[g*2+1][1] = r[3];
            }
            #pragma unroll
            for (int mt = 0; mt < 2; mt++)
                #pragma unroll
                for (int nt = 0; nt < 8; nt++) mma16816(acc[mt][nt], aq[mt], bf[nt]);
        }
        #pragma unroll
        for (int mt = 0; mt < 2; mt++) {
            int r0 = w*32 + mt*16 + (lane >> 2);
            float inv0 = Linv[r0], inv1 = Linv[r0 + 8];
            float* O0 = g_VVV + ((size_t)bh * Sq + s0 + r0) * 64;
            float* O1 = g_VVV + ((size_t)bh * Sq + s0 + r0 + 8) * 64;
            #pragma unroll
            for (int nt = 0; nt < 8; nt++) {
                int c = nt*8 + (lane & 3) * 2;
                *(float2*)(O0 + c) = make_float2(acc[mt][nt][0] * inv0, acc[mt][nt][1] * inv0);
                *(float2*)(O1 + c) = make_float2(acc[mt][nt][2] * inv1, acc[mt][nt][3] * inv1);
            }
        }
    }
}

// ---------------------------------------------------------------------------
// LayerNorm (1024), x = in1 + res.
// ---------------------------------------------------------------------------
__global__ void k_ln(const float* __restrict__ rese, const float* __restrict__ g,
                     const float* __restrict__ bb, float* __restrict__ oute, int sel) {
    const float* in1 = sel ? g_O2 : g_VVV;
    const float* res = sel ? g_O1 : rese;
    float* out = sel ? oute : g_O1;
    __shared__ float sm1[8];
    __shared__ float sm2[8];
    size_t base = (size_t)blockIdx.x * 1024;
    int t = threadIdx.x;
    float v[4];
    float sum = 0.f;
    #pragma unroll
    for (int i = 0; i < 4; i++) {
        int c = t + i * 256;
        v[i] = in1[base + c] + res[base + c];
        sum += v[i];
    }
    #pragma unroll
    for (int o = 16; o > 0; o >>= 1) sum += __shfl_xor_sync(0xffffffffu, sum, o);
    if ((t & 31) == 0) sm1[t >> 5] = sum;
    __syncthreads();
    sum = 0.f;
    #pragma unroll
    for (int i = 0; i < 8; i++) sum += sm1[i];
    float mean = sum * (1.f / 1024.f);
    float sq = 0.f;
    #pragma unroll
    for (int i = 0; i < 4; i++) { float d = v[i] - mean; sq += d * d; }
    #pragma unroll
    for (int o = 16; o > 0; o >>= 1) sq += __shfl_xor_sync(0xffffffffu, sq, o);
    if ((t & 31) == 0) sm2[t >> 5] = sq;
    __syncthreads();
    sq = 0.f;
    #pragma unroll
    for (int i = 0; i < 8; i++) sq += sm2[i];
    float rstd = rsqrtf(sq * (1.f / 1024.f) + 1e-5f);
    #pragma unroll
    for (int i = 0; i < 4; i++) {
        int c = t + i * 256;
        float o = (v[i] - mean) * rstd * g[c] + bb[c];
        out[base + c] = o;
        if (sel == 0) g_Ah[base + c] = __float2half(o);
    }
}

// ===========================================================================
// Host side — hgemm is the 5th kernel launch (ncu -s 5 captures it).
// ===========================================================================
extern "C" void kernel_launch(void* const* d_in, const int* in_sizes, int n_in,
                              void* d_out, int out_size) {
    const float* Xq  = (const float*)d_in[0];
    const float* Xk  = (const float*)d_in[1];
    const float* Xv  = (const float*)d_in[2];
    const float* Wq1 = (const float*)d_in[3];
    const float* Wq2 = (const float*)d_in[4];
    const float* Wk1 = (const float*)d_in[5];
    const float* Wk2 = (const float*)d_in[6];
    const float* Wv  = (const float*)d_in[7];
    const float* Wfc = (const float*)d_in[8];
    const float* Am  = (const float*)d_in[9];
    const float* lng = (const float*)d_in[10];
    const float* lnb = (const float*)d_in[11];
    float* out = (float*)d_out;
    size_t attn_off = (out_size > OUT_MAIN) ? (size_t)(out_size - OUT_MAIN) : 0;
    float* attn = out + attn_off;

    void *pO2, *pVV, *pL;
    cudaGetSymbolAddress(&pO2, g_O2);
    cudaGetSymbolAddress(&pVV, g_VV);
    cudaGetSymbolAddress(&pL,  g_L);

    cudaFuncSetAttribute(k_hgemm,  cudaFuncAttributeMaxDynamicSharedMemorySize, HG_SMEM);
    cudaFuncSetAttribute(k_proj1,  cudaFuncAttributeMaxDynamicSharedMemorySize, P1_SMEM);
    cudaFuncSetAttribute(k_stage2, cudaFuncAttributeMaxDynamicSharedMemorySize, S2_SMEM);

    // launches 1-4
    k_half<<<16384, 256>>>(Xv);
    k_halfT<<<dim3(32, 32), dim3(32, 8)>>>(Wv, 0);
    k_prepW<<<16, 256>>>(Wq2, Wk2, Am);
    k_zeroT<<<512, 256>>>();

    // launch 5: profiled by ncu
    k_hgemm<<<dim3(8, 128), 512, HG_SMEM>>>(nullptr, 0);    // V -> g_Vh

    k_proj1<<<dim3(4, 256), 256, P1_SMEM>>>(Xq, Wq1, 0);
    k_proj1<<<dim3(4, 256), 256, P1_SMEM>>>(Xk, Wk1, 1);

    cudaMemsetAsync(pL,  0, (size_t)BHn * DHq * sizeof(float));
    cudaMemsetAsync(pVV, 0, (size_t)BHn * DHq * DHq * sizeof(float));
    k_s1exp<<<dim3(32, 128), 256>>>(attn);
    k_vv<<<dim3(4, 128), 256>>>(attn);
    k_stage2<<<dim3(16, 128), 128, S2_SMEM>>>();
    k_ln<<<16384, 256>>>(Xq, lng, lnb, nullptr, 0);

    k_halfT<<<dim3(32, 32), dim3(32, 8)>>>(Wfc, 1);
    k_hgemm<<<dim3(8, 128), 512, HG_SMEM>>>((float*)pO2, 1);
    k_ln<<<16384, 256>>>(nullptr, lng, lnb, out, 1);
}